// round 4
// baseline (speedup 1.0000x reference)
#include <cuda_runtime.h>
#include <cuda_bf16.h>
#include <math.h>
#include <stdint.h>

#define Bq 16
#define Sq 2048
#define Hq 1024
#define Dq 512
#define MSq (Bq * Sq)   // 32768

// ---------------- scratch (__device__ globals; no allocations) ----------------
__device__ __nv_bfloat16 g_hs_hi[(size_t)MSq * Hq];
__device__ __nv_bfloat16 g_hs_lo[(size_t)MSq * Hq];
__device__ __nv_bfloat16 g_wcat_hi[(size_t)3 * Dq * Hq];   // [Wq;Wk;W1]^T rows 0..1535, K-major
__device__ __nv_bfloat16 g_wcat_lo[(size_t)3 * Dq * Hq];
__device__ __nv_bfloat16 g_q_hi[(size_t)MSq * Dq];
__device__ __nv_bfloat16 g_q_lo[(size_t)MSq * Dq];
__device__ __nv_bfloat16 g_k_hi[(size_t)MSq * Dq];
__device__ __nv_bfloat16 g_k_lo[(size_t)MSq * Dq];
__device__ float         g_hw1[(size_t)MSq * Dq];          // fp32 [B*S, D]
__device__ __nv_bfloat16 g_hw1t_hi[(size_t)Bq * Dq * Sq];  // [b][n][t]
__device__ __nv_bfloat16 g_hw1t_lo[(size_t)Bq * Dq * Sq];
__device__ float         g_scores[(size_t)Bq * Sq * Sq];
__device__ __nv_bfloat16 g_p_hi[(size_t)Bq * Sq * Sq];
__device__ __nv_bfloat16 g_p_lo[(size_t)Bq * Sq * Sq];
__device__ float         g_h[(size_t)MSq * Dq];
__device__ int           g_len[Bq];
__device__ float         g_ratlen[Bq];

// ---------------- helpers ----------------
__device__ __forceinline__ uint32_t smem_u32(const void* p) {
    uint32_t a;
    asm("{ .reg .u64 t; cvta.to.shared.u64 t, %1; cvt.u32.u64 %0, t; }" : "=r"(a) : "l"(p));
    return a;
}
__device__ __forceinline__ void cpa16(uint32_t s, const void* g) {
    asm volatile("cp.async.cg.shared.global [%0], [%1], 16;" :: "r"(s), "l"(g));
}
__device__ __forceinline__ void cpa_commit() {
    asm volatile("cp.async.commit_group;" ::: "memory");
}
template<int N> __device__ __forceinline__ void cpa_wait() {
    asm volatile("cp.async.wait_group %0;" :: "n"(N) : "memory");
}
__device__ __forceinline__ void ldm4(uint32_t* d, uint32_t a) {
    asm volatile("ldmatrix.sync.aligned.m8n8.x4.shared.b16 {%0,%1,%2,%3}, [%4];"
        : "=r"(d[0]), "=r"(d[1]), "=r"(d[2]), "=r"(d[3]) : "r"(a));
}
__device__ __forceinline__ void mma16816(float* c, const uint32_t* a, const uint32_t* b) {
    asm volatile("mma.sync.aligned.m16n8k16.row.col.f32.bf16.bf16.f32 "
        "{%0,%1,%2,%3}, {%4,%5,%6,%7}, {%8,%9}, {%0,%1,%2,%3};"
        : "+f"(c[0]), "+f"(c[1]), "+f"(c[2]), "+f"(c[3])
        : "r"(a[0]), "r"(a[1]), "r"(a[2]), "r"(a[3]), "r"(b[0]), "r"(b[1]));
}
__device__ __forceinline__ void split2(float v, __nv_bfloat16& h, __nv_bfloat16& l) {
    h = __float2bfloat16(v);
    l = __float2bfloat16(v - __bfloat162float(h));
}
__device__ __forceinline__ uint32_t swz(int r, int chunk) {
    return ((uint32_t)r << 7) + (uint32_t)((chunk ^ (r & 7)) << 4);
}

// ---------------------------------------------------------------------------
// Split-bf16 mma.sync GEMM, 128x128 tile, K-chunk 64, 3-stage cp.async.
// MODE 0: fused projections (M-block skip by batch; N ranges -> q/k split or hw1 f32)
// MODE 1: scores (skip m0>=len || n0>=len; f32 out, alpha)
// MODE 2: probs@hw1t (skip m0>=len; K clamped to ceil(len/64); f32 out)
// ---------------------------------------------------------------------------
#define MM_SMEM 196608   // 3 stages x 64KB

template<int MODE>
__global__ void __launch_bounds__(256)
mma_gemm(const __nv_bfloat16* __restrict__ Ah, const __nv_bfloat16* __restrict__ Al,
         const __nv_bfloat16* __restrict__ Bh, const __nv_bfloat16* __restrict__ Bl,
         const float* __restrict__ bias1, const float* __restrict__ bias2, float alpha,
         float* __restrict__ Cf, __nv_bfloat16* __restrict__ C1h, __nv_bfloat16* __restrict__ C1l,
         __nv_bfloat16* __restrict__ C2h, __nv_bfloat16* __restrict__ C2l,
         int K, int ldc, long long sA, long long sB, long long sC)
{
    extern __shared__ char dsm[];
    const uint32_t sb0 = smem_u32(dsm);
    const int tid  = threadIdx.x;
    const int lane = tid & 31;
    const int wid  = tid >> 5;
    const int wm   = wid & 1;
    const int wn   = wid >> 1;

    const long long z = blockIdx.z;
    const int m0 = blockIdx.y * 128;
    const int n0 = blockIdx.x * 128;

    int NK = K >> 6;
    if (MODE == 0) {
        const int b = m0 >> 11;
        if ((m0 & 2047) >= g_len[b]) return;
    } else if (MODE == 1) {
        const int len = g_len[z];
        if (m0 >= len || n0 >= len) return;
    } else {
        const int len = g_len[z];
        if (m0 >= len) return;
        const int nk2 = (len + 63) >> 6;
        if (nk2 < NK) NK = nk2;
    }

    const __nv_bfloat16* pAh = Ah + z * sA;
    const __nv_bfloat16* pAl = Al + z * sA;
    const __nv_bfloat16* pBh = Bh + z * sB;
    const __nv_bfloat16* pBl = Bl + z * sB;

    const int r_ld  = tid >> 1;
    const int cu_ld = (tid & 1) << 2;
    const long long arow = (long long)(m0 + r_ld) * K;
    const long long brow = (long long)(n0 + r_ld) * K;

    auto issue = [&](int kt) {
        const uint32_t so = sb0 + (uint32_t)(kt % 3) * 65536u;
        const int k0 = kt << 6;
#pragma unroll
        for (int i = 0; i < 4; i++) {
            const int ch = cu_ld + i;
            const uint32_t sw = swz(r_ld, ch);
            const int go = k0 + ch * 8;
            cpa16(so +     0 + sw, pAh + arow + go);
            cpa16(so + 16384 + sw, pAl + arow + go);
            cpa16(so + 32768 + sw, pBh + brow + go);
            cpa16(so + 49152 + sw, pBl + brow + go);
        }
        cpa_commit();
    };

    float acc[4][4][4];
#pragma unroll
    for (int i = 0; i < 4; i++)
#pragma unroll
        for (int j = 0; j < 4; j++)
#pragma unroll
            for (int e = 0; e < 4; e++) acc[i][j][e] = 0.f;

    const int l15 = lane & 15, lhi = lane >> 4;
    int rA[4], rB[2];
#pragma unroll
    for (int mi = 0; mi < 4; mi++) rA[mi] = wm * 64 + mi * 16 + l15;
#pragma unroll
    for (int bj = 0; bj < 2; bj++) rB[bj] = wn * 32 + bj * 16 + l15;

    issue(0);
    if (NK > 1) issue(1);

#pragma unroll 1
    for (int kt = 0; kt < NK; kt++) {
        if (kt + 2 < NK) { issue(kt + 2); cpa_wait<2>(); }
        else if (kt + 1 < NK) cpa_wait<1>();
        else cpa_wait<0>();
        __syncthreads();

        const uint32_t uA = sb0 + (uint32_t)(kt % 3) * 65536u;
        const uint32_t uAl = uA + 16384, uBh = uA + 32768, uBl = uA + 49152;

#pragma unroll
        for (int ks = 0; ks < 4; ks++) {
            const int ch = ks * 2 + lhi;
            uint32_t ah[4][4], al[4][4], bh[4][2], bl[4][2];
#pragma unroll
            for (int mi = 0; mi < 4; mi++) ldm4(ah[mi], uA  + swz(rA[mi], ch));
#pragma unroll
            for (int mi = 0; mi < 4; mi++) ldm4(al[mi], uAl + swz(rA[mi], ch));
#pragma unroll
            for (int bj = 0; bj < 2; bj++) {
                uint32_t q[4];
                ldm4(q, uBh + swz(rB[bj], ch));
                bh[bj*2][0] = q[0]; bh[bj*2+1][0] = q[1];
                bh[bj*2][1] = q[2]; bh[bj*2+1][1] = q[3];
                ldm4(q, uBl + swz(rB[bj], ch));
                bl[bj*2][0] = q[0]; bl[bj*2+1][0] = q[1];
                bl[bj*2][1] = q[2]; bl[bj*2+1][1] = q[3];
            }
#pragma unroll
            for (int mi = 0; mi < 4; mi++)
#pragma unroll
                for (int nj = 0; nj < 4; nj++) {
                    mma16816(acc[mi][nj], ah[mi], bh[nj]);
                    mma16816(acc[mi][nj], ah[mi], bl[nj]);
                    mma16816(acc[mi][nj], al[mi], bh[nj]);
                }
        }
        __syncthreads();
    }

    // ---- epilogue ----
    const int r4 = lane >> 2, c2 = (lane & 3) << 1;
#pragma unroll
    for (int mi = 0; mi < 4; mi++) {
        const long long gm = (long long)(m0 + wm * 64 + mi * 16 + r4);
#pragma unroll
        for (int nj = 0; nj < 4; nj++) {
            const int gn = n0 + wn * 32 + nj * 8 + c2;
            float v0 = alpha * acc[mi][nj][0];
            float v1 = alpha * acc[mi][nj][1];
            float v2 = alpha * acc[mi][nj][2];
            float v3 = alpha * acc[mi][nj][3];

            if (MODE == 0) {
                const int rng = gn >> 9;          // 0=q, 1=k, 2=hw1
                const int col = gn & 511;
                const long long o0 = gm * Dq + col;
                const long long o1 = (gm + 8) * Dq + col;
                if (rng == 2) {
                    *(float2*)&Cf[o0] = make_float2(v0, v1);
                    *(float2*)&Cf[o1] = make_float2(v2, v3);
                } else {
                    const float* bia = (rng == 0) ? bias1 : bias2;
                    const float bx = bia[col], by = bia[col + 1];
                    v0 += bx; v1 += by; v2 += bx; v3 += by;
                    __nv_bfloat16* Dh = (rng == 0) ? C1h : C2h;
                    __nv_bfloat16* Dl = (rng == 0) ? C1l : C2l;
                    union { __nv_bfloat16 b[2]; uint32_t u; } ph, pl;
                    __nv_bfloat16 h0,l0,h1,l1;
                    split2(v0,h0,l0); split2(v1,h1,l1);
                    ph.b[0]=h0; ph.b[1]=h1; pl.b[0]=l0; pl.b[1]=l1;
                    *(uint32_t*)&Dh[o0] = ph.u; *(uint32_t*)&Dl[o0] = pl.u;
                    split2(v2,h0,l0); split2(v3,h1,l1);
                    ph.b[0]=h0; ph.b[1]=h1; pl.b[0]=l0; pl.b[1]=l1;
                    *(uint32_t*)&Dh[o1] = ph.u; *(uint32_t*)&Dl[o1] = pl.u;
                }
            } else {
                float* pC = Cf + z * sC;
                const long long o0 = gm * ldc + gn;
                const long long o1 = (gm + 8) * ldc + gn;
                *(float2*)&pC[o0] = make_float2(v0, v1);
                *(float2*)&pC[o1] = make_float2(v2, v3);
            }
        }
    }
}

// ---------------- conversions ----------------
__global__ void convert_hs_kernel(const float* __restrict__ hs) {
    const size_t i = ((size_t)blockIdx.x * 256 + threadIdx.x) * 8;
    const int row = (int)(i >> 10);
    if ((row & 2047) >= g_len[row >> 11]) return;   // unused rows: skip
    float4 a = *(const float4*)(hs + i);
    float4 b = *(const float4*)(hs + i + 4);
    union { uint4 q; __nv_bfloat16 v[8]; } hi, lo;
    split2(a.x, hi.v[0], lo.v[0]); split2(a.y, hi.v[1], lo.v[1]);
    split2(a.z, hi.v[2], lo.v[2]); split2(a.w, hi.v[3], lo.v[3]);
    split2(b.x, hi.v[4], lo.v[4]); split2(b.y, hi.v[5], lo.v[5]);
    split2(b.z, hi.v[6], lo.v[6]); split2(b.w, hi.v[7], lo.v[7]);
    *(uint4*)&g_hs_hi[i] = hi.q;
    *(uint4*)&g_hs_lo[i] = lo.q;
}

// W [Hq, Dq] fp32 -> g_wcat rows [base, base+Dq) K-major hi/lo bf16
__global__ void convert_wT_kernel(const float* __restrict__ W, int base) {
    __shared__ float t[32][33];
    const int nx = blockIdx.x * 32, ky = blockIdx.y * 32;
    const int x = threadIdx.x, y = threadIdx.y;
#pragma unroll
    for (int i = 0; i < 32; i += 8)
        t[y + i][x] = W[(size_t)(ky + y + i) * Dq + nx + x];
    __syncthreads();
#pragma unroll
    for (int i = 0; i < 32; i += 8) {
        __nv_bfloat16 h, l; split2(t[x][y + i], h, l);
        const size_t o = (size_t)(base + nx + y + i) * Hq + ky + x;
        g_wcat_hi[o] = h; g_wcat_lo[o] = l;
    }
}

// g_hw1 [(b*S+t), n] fp32 -> g_hw1t [b][n][t] hi/lo bf16
__global__ void transpose_hw1_kernel() {
    __shared__ float t[32][33];
    const int b = blockIdx.z;
    const int nx = blockIdx.x * 32, sy = blockIdx.y * 32;
    const int x = threadIdx.x, y = threadIdx.y;
#pragma unroll
    for (int i = 0; i < 32; i += 8)
        t[y + i][x] = g_hw1[(size_t)(b * Sq + sy + y + i) * Dq + nx + x];
    __syncthreads();
#pragma unroll
    for (int i = 0; i < 32; i += 8) {
        __nv_bfloat16 h, l; split2(t[x][y + i], h, l);
        const size_t o = (size_t)(b * Dq + nx + y + i) * Sq + sy + x;
        g_hw1t_hi[o] = h; g_hw1t_lo[o] = l;
    }
}

// ---------------- non-GEMM kernels ----------------
__global__ void lens_kernel(const int* __restrict__ mask) {
    __shared__ int red[256];
    const int b = blockIdx.x, tid = threadIdx.x;
    int s = 0;
    for (int t = tid; t < Sq; t += 256) s += mask[b * Sq + t];
    red[tid] = s; __syncthreads();
    for (int w = 128; w > 0; w >>= 1) { if (tid < w) red[tid] += red[tid + w]; __syncthreads(); }
    if (tid == 0) g_len[b] = red[0];
}

__global__ void softmax_scores_kernel() {
    __shared__ float buf[Sq];
    __shared__ float red[256];
    const int row = blockIdx.x;
    const int len = g_len[row >> 11];
    const float* x = g_scores + (size_t)row * Sq;
    const int tid = threadIdx.x;

    float m = -1e30f;
    for (int t = tid; t < Sq; t += 256) { float v = x[t]; buf[t] = v; if (t < len) m = fmaxf(m, v); }
    red[tid] = m; __syncthreads();
    for (int w = 128; w > 0; w >>= 1) { if (tid < w) red[tid] = fmaxf(red[tid], red[tid + w]); __syncthreads(); }
    m = red[0]; __syncthreads();

    float s = 0.f;
    for (int t = tid; t < len; t += 256) { float e = expf(buf[t] - m); buf[t] = e; s += e; }
    red[tid] = s; __syncthreads();
    for (int w = 128; w > 0; w >>= 1) { if (tid < w) red[tid] += red[tid + w]; __syncthreads(); }
    const float Z = red[0];

    for (int t = tid; t < Sq; t += 256) {
        const float p = (t < len) ? buf[t] / Z : 0.f;
        __nv_bfloat16 h, l; split2(p, h, l);
        g_p_hi[(size_t)row * Sq + t] = h;
        g_p_lo[(size_t)row * Sq + t] = l;
    }
}

__global__ void ln_score_kernel(const float* __restrict__ b1,
                                const float* __restrict__ lng, const float* __restrict__ lnb,
                                const float* __restrict__ W2,  const float* __restrict__ b2,
                                float* __restrict__ ts_out)
{
    __shared__ float red[128];
    const int row = blockIdx.x;
    const int tid = threadIdx.x;
    const int b = row >> 11, sIdx = row & (Sq - 1);
    if (sIdx >= g_len[b]) { if (tid == 0) ts_out[row] = -10000.f; return; }
    const float* h = g_h + (size_t)row * Dq;

    float v[4];
    float s = 0.f;
#pragma unroll
    for (int i = 0; i < 4; i++) { v[i] = h[tid + i * 128] + b1[tid + i * 128]; s += v[i]; }
    red[tid] = s; __syncthreads();
    for (int w = 64; w > 0; w >>= 1) { if (tid < w) red[tid] += red[tid + w]; __syncthreads(); }
    const float mu = red[0] / (float)Dq;
    __syncthreads();

    s = 0.f;
#pragma unroll
    for (int i = 0; i < 4; i++) { float d = v[i] - mu; s += d * d; }
    red[tid] = s; __syncthreads();
    for (int w = 64; w > 0; w >>= 1) { if (tid < w) red[tid] += red[tid + w]; __syncthreads(); }
    const float rstd = rsqrtf(red[0] / (float)Dq + 1e-5f);
    __syncthreads();

    s = 0.f;
#pragma unroll
    for (int i = 0; i < 4; i++) {
        const int d = tid + i * 128;
        float y = (v[i] - mu) * rstd * lng[d] + lnb[d];
        y = fmaxf(y, 0.f);
        s += y * W2[d];
    }
    red[tid] = s; __syncthreads();
    for (int w = 64; w > 0; w >>= 1) { if (tid < w) red[tid] += red[tid + w]; __syncthreads(); }
    if (tid == 0) ts_out[row] = red[0] + b2[0];
}

__global__ void rationale_kernel(const float* __restrict__ ts_all, float* __restrict__ rat_out)
{
    __shared__ float cum[Sq];
    __shared__ float rv[256];
    __shared__ int   ri[256];
    const int b = blockIdx.x, tid = threadIdx.x;
    const float* ts = ts_all + b * Sq;

    for (int t = tid; t < Sq; t += 256) cum[t] = ts[t];
    __syncthreads();
    if (tid == 0) { float a = 0.f; for (int t = 0; t < Sq; t++) { a += cum[t]; cum[t] = a; } }
    __syncthreads();

    const int vl = g_len[b];
    float best = -1e38f; int bi = 1 << 30;
    for (int idx = tid; idx < 18 * Sq; idx += 256) {
        const int Li = idx >> 11;
        const int s  = idx & (Sq - 1);
        const int L  = 3 + Li;
        if (L <= vl && s <= vl - L) {
            int e = s + L - 1; if (e > Sq - 1) e = Sq - 1;
            const float val = cum[e] / (float)L + 0.01f * ((float)L / 20.0f);
            if (val > best || (val == best && idx < bi)) { best = val; bi = idx; }
        }
    }
    rv[tid] = best; ri[tid] = bi; __syncthreads();
    for (int w = 128; w > 0; w >>= 1) {
        if (tid < w) {
            if (rv[tid + w] > rv[tid] || (rv[tid + w] == rv[tid] && ri[tid + w] < ri[tid])) {
                rv[tid] = rv[tid + w]; ri[tid] = ri[tid + w];
            }
        }
        __syncthreads();
    }
    int idx = ri[0];
    if (idx >= 18 * Sq) idx = 0;
    const int bestL = 3 + (idx >> 11);
    const int bests = idx & (Sq - 1);
    const bool shortc = (vl <= 3);

    for (int t = tid; t < Sq; t += 256) {
        const float r = shortc ? ((t < vl) ? 1.f : 0.f)
                               : ((t >= bests && t < bests + bestL) ? 1.f : 0.f);
        rat_out[b * Sq + t] = r;
    }
    if (tid == 0) g_ratlen[b] = shortc ? (float)vl : (float)bestL;
}

__global__ void token_probs_kernel(const float* __restrict__ ts, float* __restrict__ tp)
{
    __shared__ float buf[Sq];
    __shared__ float red[256];
    const int b = blockIdx.x, tid = threadIdx.x;
    const float* x = ts + b * Sq;

    float m = -1e30f;
    for (int t = tid; t < Sq; t += 256) { float v = x[t]; buf[t] = v; m = fmaxf(m, v); }
    red[tid] = m; __syncthreads();
    for (int w = 128; w > 0; w >>= 1) { if (tid < w) red[tid] = fmaxf(red[tid], red[tid + w]); __syncthreads(); }
    m = red[0]; __syncthreads();

    float s = 0.f;
    for (int t = tid; t < Sq; t += 256) { float e = expf(buf[t] - m); buf[t] = e; s += e; }
    red[tid] = s; __syncthreads();
    for (int w = 128; w > 0; w >>= 1) { if (tid < w) red[tid] += red[tid + w]; __syncthreads(); }
    const float Z = red[0];

    for (int t = tid; t < Sq; t += 256) tp[b * Sq + t] = buf[t] / Z;
}

__global__ void attended_pooled_kernel(const float* __restrict__ hs,
                                       const float* __restrict__ rat,
                                       float* __restrict__ att, float* __restrict__ pooled)
{
    __shared__ float r[Sq];
    const int b = blockIdx.y;
    const int h = blockIdx.x * 256 + threadIdx.x;
    for (int t = threadIdx.x; t < Sq; t += 256) r[t] = rat[b * Sq + t];
    __syncthreads();

    const float* hsb = hs  + (size_t)b * Sq * Hq;
    float*      attb = att + (size_t)b * Sq * Hq;
    float a0 = 0.f, a1 = 0.f, a2 = 0.f, a3 = 0.f;
    for (int s = 0; s < Sq; s += 4) {
        float v0 = (r[s+0] != 0.f) ? hsb[(size_t)(s+0) * Hq + h] * r[s+0] : 0.f;
        float v1 = (r[s+1] != 0.f) ? hsb[(size_t)(s+1) * Hq + h] * r[s+1] : 0.f;
        float v2 = (r[s+2] != 0.f) ? hsb[(size_t)(s+2) * Hq + h] * r[s+2] : 0.f;
        float v3 = (r[s+3] != 0.f) ? hsb[(size_t)(s+3) * Hq + h] * r[s+3] : 0.f;
        attb[(size_t)(s+0) * Hq + h] = v0;
        attb[(size_t)(s+1) * Hq + h] = v1;
        attb[(size_t)(s+2) * Hq + h] = v2;
        attb[(size_t)(s+3) * Hq + h] = v3;
        a0 += v0; a1 += v1; a2 += v2; a3 += v3;
    }
    pooled[b * Hq + h] = ((a0 + a1) + (a2 + a3)) / (g_ratlen[b] + 1e-6f);
}

// ---------------------------------------------------------------------------
extern "C" void kernel_launch(void* const* d_in, const int* in_sizes, int n_in,
                              void* d_out, int out_size)
{
    (void)in_sizes; (void)n_in; (void)out_size;
    const float* hs  = (const float*)d_in[0];
    const int*   am  = (const int*)  d_in[1];
    const float* Wq  = (const float*)d_in[2];
    const float* bq  = (const float*)d_in[3];
    const float* Wk  = (const float*)d_in[4];
    const float* bk  = (const float*)d_in[5];
    const float* W1  = (const float*)d_in[6];
    const float* b1  = (const float*)d_in[7];
    const float* lng = (const float*)d_in[8];
    const float* lnb = (const float*)d_in[9];
    const float* W2  = (const float*)d_in[10];
    const float* b2  = (const float*)d_in[11];

    float* out    = (float*)d_out;
    float* ts     = out;
    float* rat    = out + (size_t)MSq;
    float* tp     = out + (size_t)2 * MSq;
    float* att    = out + (size_t)3 * MSq;
    float* pooled = out + (size_t)3 * MSq + (size_t)MSq * Hq;

    __nv_bfloat16 *hsh, *hsl, *wch, *wcl;
    __nv_bfloat16 *qh, *ql, *kh, *kl, *h1th, *h1tl, *ph, *pl;
    float *hw1, *sc, *hbuf;
    cudaGetSymbolAddress((void**)&hsh, g_hs_hi);  cudaGetSymbolAddress((void**)&hsl, g_hs_lo);
    cudaGetSymbolAddress((void**)&wch, g_wcat_hi); cudaGetSymbolAddress((void**)&wcl, g_wcat_lo);
    cudaGetSymbolAddress((void**)&qh,  g_q_hi);   cudaGetSymbolAddress((void**)&ql,  g_q_lo);
    cudaGetSymbolAddress((void**)&kh,  g_k_hi);   cudaGetSymbolAddress((void**)&kl,  g_k_lo);
    cudaGetSymbolAddress((void**)&h1th, g_hw1t_hi); cudaGetSymbolAddress((void**)&h1tl, g_hw1t_lo);
    cudaGetSymbolAddress((void**)&ph,  g_p_hi);   cudaGetSymbolAddress((void**)&pl,  g_p_lo);
    cudaGetSymbolAddress((void**)&hw1, g_hw1);
    cudaGetSymbolAddress((void**)&sc,  g_scores);
    cudaGetSymbolAddress((void**)&hbuf, g_h);

    cudaFuncSetAttribute(mma_gemm<0>, cudaFuncAttributeMaxDynamicSharedMemorySize, MM_SMEM);
    cudaFuncSetAttribute(mma_gemm<1>, cudaFuncAttributeMaxDynamicSharedMemorySize, MM_SMEM);
    cudaFuncSetAttribute(mma_gemm<2>, cudaFuncAttributeMaxDynamicSharedMemorySize, MM_SMEM);

    lens_kernel<<<Bq, 256>>>(am);
    convert_hs_kernel<<<(int)(((size_t)MSq * Hq) / 8 / 256), 256>>>(hs);
    dim3 wg(Dq / 32, Hq / 32);
    convert_wT_kernel<<<wg, dim3(32, 8)>>>(Wq, 0);
    convert_wT_kernel<<<wg, dim3(32, 8)>>>(Wk, 512);
    convert_wT_kernel<<<wg, dim3(32, 8)>>>(W1, 1024);

    // fused projections: M=32768, N=1536, K=1024
    dim3 gP(12, MSq / 128, 1);
    mma_gemm<0><<<gP, 256, MM_SMEM>>>(hsh, hsl, wch, wcl, bq, bk, 1.f,
        hw1, qh, ql, kh, kl, Hq, Dq, 0, 0, 0);

    // scores = Q @ K^T / sqrt(D): per batch 2048x2048, K=512
    dim3 gS(Sq / 128, Sq / 128, Bq);
    mma_gemm<1><<<gS, 256, MM_SMEM>>>(qh, ql, kh, kl, nullptr, nullptr,
        0.044194173824159216f, sc, nullptr, nullptr, nullptr, nullptr,
        Dq, Sq, (long long)Sq * Dq, (long long)Sq * Dq, (long long)Sq * Sq);

    transpose_hw1_kernel<<<dim3(Dq / 32, Sq / 32, Bq), dim3(32, 8)>>>();
    softmax_scores_kernel<<<MSq, 256>>>();

    // h = probs @ HSW1: per batch 2048x512, K=2048 (clamped to len)
    dim3 gH(Dq / 128, Sq / 128, Bq);
    mma_gemm<2><<<gH, 256, MM_SMEM>>>(ph, pl, h1th, h1tl, nullptr, nullptr, 1.f,
        hbuf, nullptr, nullptr, nullptr, nullptr,
        Sq, Dq, (long long)Sq * Sq, (long long)Dq * Sq, (long long)Sq * Dq);

    ln_score_kernel<<<MSq, 128>>>(b1, lng, lnb, W2, b2, ts);
    rationale_kernel<<<Bq, 256>>>(ts, rat);
    token_probs_kernel<<<Bq, 256>>>(ts, tp);
    attended_pooled_kernel<<<dim3(Hq / 256, Bq), 256>>>(hs, rat, att, pooled);
}

// round 5
// speedup vs baseline: 1.5163x; 1.5163x over previous
#include <cuda_runtime.h>
#include <cuda_bf16.h>
#include <math.h>
#include <stdint.h>

#define Bq 16
#define Sq 2048
#define Hq 1024
#define Dq 512
#define MSq (Bq * Sq)   // 32768

// ---------------- scratch (__device__ globals; no allocations) ----------------
__device__ __nv_bfloat16 g_hs_hi[(size_t)MSq * Hq];
__device__ __nv_bfloat16 g_hs_lo[(size_t)MSq * Hq];
__device__ __nv_bfloat16 g_wqT_hi[(size_t)Dq * Hq];
__device__ __nv_bfloat16 g_wqT_lo[(size_t)Dq * Hq];
__device__ __nv_bfloat16 g_wkT_hi[(size_t)Dq * Hq];
__device__ __nv_bfloat16 g_wkT_lo[(size_t)Dq * Hq];
__device__ __nv_bfloat16 g_w1T_hi[(size_t)Dq * Hq];
__device__ __nv_bfloat16 g_w1T_lo[(size_t)Dq * Hq];
__device__ __nv_bfloat16 g_q_hi[(size_t)MSq * Dq];
__device__ __nv_bfloat16 g_q_lo[(size_t)MSq * Dq];
__device__ __nv_bfloat16 g_k_hi[(size_t)MSq * Dq];
__device__ __nv_bfloat16 g_k_lo[(size_t)MSq * Dq];
__device__ float         g_hw1[(size_t)MSq * Dq];                 // fp32, [B*S, D]
__device__ __nv_bfloat16 g_hw1t_hi[(size_t)Bq * Dq * Sq];         // [b][n][t]
__device__ __nv_bfloat16 g_hw1t_lo[(size_t)Bq * Dq * Sq];
__device__ float         g_scores[(size_t)Bq * Sq * Sq];          // 256 MB
__device__ __nv_bfloat16 g_p_hi[(size_t)Bq * Sq * Sq];
__device__ __nv_bfloat16 g_p_lo[(size_t)Bq * Sq * Sq];
__device__ float         g_h[(size_t)MSq * Dq];
__device__ int           g_len[Bq];
__device__ float         g_ratlen[Bq];

// ---------------- helpers ----------------
__device__ __forceinline__ uint32_t smem_u32(const void* p) {
    uint32_t a;
    asm("{ .reg .u64 t; cvta.to.shared.u64 t, %1; cvt.u32.u64 %0, t; }" : "=r"(a) : "l"(p));
    return a;
}
__device__ __forceinline__ void cpa16(uint32_t s, const void* g) {
    asm volatile("cp.async.cg.shared.global [%0], [%1], 16;" :: "r"(s), "l"(g));
}
__device__ __forceinline__ void cpa_commit() {
    asm volatile("cp.async.commit_group;" ::: "memory");
}
template<int N> __device__ __forceinline__ void cpa_wait() {
    asm volatile("cp.async.wait_group %0;" :: "n"(N) : "memory");
}
__device__ __forceinline__ void ldm4(uint32_t* d, uint32_t a) {
    asm volatile("ldmatrix.sync.aligned.m8n8.x4.shared.b16 {%0,%1,%2,%3}, [%4];"
        : "=r"(d[0]), "=r"(d[1]), "=r"(d[2]), "=r"(d[3]) : "r"(a));
}
__device__ __forceinline__ void mma16816(float* c, const uint32_t* a, const uint32_t* b) {
    asm volatile("mma.sync.aligned.m16n8k16.row.col.f32.bf16.bf16.f32 "
        "{%0,%1,%2,%3}, {%4,%5,%6,%7}, {%8,%9}, {%0,%1,%2,%3};"
        : "+f"(c[0]), "+f"(c[1]), "+f"(c[2]), "+f"(c[3])
        : "r"(a[0]), "r"(a[1]), "r"(a[2]), "r"(a[3]), "r"(b[0]), "r"(b[1]));
}
__device__ __forceinline__ void split2(float v, __nv_bfloat16& h, __nv_bfloat16& l) {
    h = __float2bfloat16(v);
    l = __float2bfloat16(v - __bfloat162float(h));
}
// SW128-style swizzle inside a 128-byte row: chunk' = chunk ^ (row & 7)
__device__ __forceinline__ uint32_t swz(int r, int chunk) {
    return ((uint32_t)r << 7) + (uint32_t)((chunk ^ (r & 7)) << 4);
}

// ---------------------------------------------------------------------------
// Split-bf16 mma.sync GEMM (round-3 engine: 128x128 tile, K-chunk 64,
// 2-stage cp.async double buffer, 8 warps 64x32 each).
// MODE 0: projection, SPLIT bf16 out + bias; skip row-blocks >= len[b]
// MODE 1: projection, f32 out (hw1);        skip row-blocks >= len[b]
// MODE 2: scores, f32 out, alpha;           skip m0>=len[z] || n0>=len[z]
// MODE 3: probs GEMM, f32 out;              skip m0>=len[z], clamp K to len
// ---------------------------------------------------------------------------
#define MM_SMEM 131072

template<int MODE>
__global__ void __launch_bounds__(256)
mma_gemm(const __nv_bfloat16* __restrict__ Ah, const __nv_bfloat16* __restrict__ Al,
         const __nv_bfloat16* __restrict__ Bh, const __nv_bfloat16* __restrict__ Bl,
         const float* __restrict__ bias, float alpha,
         float* __restrict__ Cf, __nv_bfloat16* __restrict__ Chi, __nv_bfloat16* __restrict__ Clo,
         int K, int ldc, long long sA, long long sB, long long sC)
{
    extern __shared__ char dsm[];
    const uint32_t sb0 = smem_u32(dsm);
    const int tid  = threadIdx.x;
    const int lane = tid & 31;
    const int wid  = tid >> 5;
    const int wm   = wid & 1;
    const int wn   = wid >> 1;

    const long long z = blockIdx.z;
    const int m0 = blockIdx.y * 128;
    const int n0 = blockIdx.x * 128;

    int NK = K >> 6;
    if (MODE == 0 || MODE == 1) {
        if ((m0 & 2047) >= g_len[m0 >> 11]) return;
    } else if (MODE == 2) {
        const int len = g_len[z];
        if (m0 >= len || n0 >= len) return;
    } else {
        const int len = g_len[z];
        if (m0 >= len) return;
        const int nk2 = (len + 63) >> 6;
        if (nk2 < NK) NK = nk2;
    }

    const __nv_bfloat16* pAh = Ah + z * sA;
    const __nv_bfloat16* pAl = Al + z * sA;
    const __nv_bfloat16* pBh = Bh + z * sB;
    const __nv_bfloat16* pBl = Bl + z * sB;

    // cp.async issue for one K-chunk into stage (kt&1)
    const int r_ld  = tid >> 1;
    const int cu_ld = (tid & 1) << 2;
    const long long arow = (long long)(m0 + r_ld) * K;
    const long long brow = (long long)(n0 + r_ld) * K;

    auto issue = [&](int kt) {
        const uint32_t so = sb0 + ((uint32_t)(kt & 1) << 16);
        const int k0 = kt << 6;
#pragma unroll
        for (int i = 0; i < 4; i++) {
            const int ch = cu_ld + i;
            const uint32_t sw = swz(r_ld, ch);
            const int go = k0 + ch * 8;
            cpa16(so +     0 + sw, pAh + arow + go);
            cpa16(so + 16384 + sw, pAl + arow + go);
            cpa16(so + 32768 + sw, pBh + brow + go);
            cpa16(so + 49152 + sw, pBl + brow + go);
        }
        cpa_commit();
    };

    float acc[4][4][4];
#pragma unroll
    for (int i = 0; i < 4; i++)
#pragma unroll
        for (int j = 0; j < 4; j++)
#pragma unroll
            for (int e = 0; e < 4; e++) acc[i][j][e] = 0.f;

    const int l15 = lane & 15, lhi = lane >> 4;
    int rA[4], rB[2];
#pragma unroll
    for (int mi = 0; mi < 4; mi++) rA[mi] = wm * 64 + mi * 16 + l15;
#pragma unroll
    for (int bj = 0; bj < 2; bj++) rB[bj] = wn * 32 + bj * 16 + l15;

    issue(0);

#pragma unroll 1
    for (int kt = 0; kt < NK; kt++) {
        if (kt + 1 < NK) { issue(kt + 1); cpa_wait<1>(); }
        else             { cpa_wait<0>(); }
        __syncthreads();

        const uint32_t uA = sb0 + ((uint32_t)(kt & 1) << 16);
        const uint32_t uAl = uA + 16384, uBh = uA + 32768, uBl = uA + 49152;

#pragma unroll
        for (int ks = 0; ks < 4; ks++) {
            const int ch = ks * 2 + lhi;
            uint32_t ah[4][4], al[4][4], bh[4][2], bl[4][2];
#pragma unroll
            for (int mi = 0; mi < 4; mi++) ldm4(ah[mi], uA  + swz(rA[mi], ch));
#pragma unroll
            for (int mi = 0; mi < 4; mi++) ldm4(al[mi], uAl + swz(rA[mi], ch));
#pragma unroll
            for (int bj = 0; bj < 2; bj++) {
                uint32_t q[4];
                ldm4(q, uBh + swz(rB[bj], ch));
                bh[bj*2][0] = q[0]; bh[bj*2+1][0] = q[1];
                bh[bj*2][1] = q[2]; bh[bj*2+1][1] = q[3];
                ldm4(q, uBl + swz(rB[bj], ch));
                bl[bj*2][0] = q[0]; bl[bj*2+1][0] = q[1];
                bl[bj*2][1] = q[2]; bl[bj*2+1][1] = q[3];
            }
#pragma unroll
            for (int mi = 0; mi < 4; mi++)
#pragma unroll
                for (int nj = 0; nj < 4; nj++) {
                    mma16816(acc[mi][nj], ah[mi], bh[nj]);
                    mma16816(acc[mi][nj], ah[mi], bl[nj]);
                    mma16816(acc[mi][nj], al[mi], bh[nj]);
                }
        }
        __syncthreads();
    }

    // ---- epilogue: direct gmem stores from fragments ----
    float*         pCf  = Cf  + z * sC;
    __nv_bfloat16* pChi = Chi + z * sC;
    __nv_bfloat16* pClo = Clo + z * sC;
    const int r4 = lane >> 2, c2 = (lane & 3) << 1;
#pragma unroll
    for (int mi = 0; mi < 4; mi++) {
        const long long gm = (long long)(m0 + wm * 64 + mi * 16 + r4);
#pragma unroll
        for (int nj = 0; nj < 4; nj++) {
            const int gn = n0 + wn * 32 + nj * 8 + c2;
            float v0 = alpha * acc[mi][nj][0];
            float v1 = alpha * acc[mi][nj][1];
            float v2 = alpha * acc[mi][nj][2];
            float v3 = alpha * acc[mi][nj][3];
            if (MODE == 0) {
                const float bx = bias[gn], by = bias[gn + 1];
                v0 += bx; v1 += by; v2 += bx; v3 += by;
            }
            const long long o0 = gm * ldc + gn;
            const long long o1 = (gm + 8) * ldc + gn;
            if (MODE == 0) {
                union { __nv_bfloat16 b[2]; uint32_t u; } ph, pl;
                __nv_bfloat16 h0,l0,h1,l1;
                split2(v0,h0,l0); split2(v1,h1,l1);
                ph.b[0]=h0; ph.b[1]=h1; pl.b[0]=l0; pl.b[1]=l1;
                *(uint32_t*)&pChi[o0] = ph.u; *(uint32_t*)&pClo[o0] = pl.u;
                split2(v2,h0,l0); split2(v3,h1,l1);
                ph.b[0]=h0; ph.b[1]=h1; pl.b[0]=l0; pl.b[1]=l1;
                *(uint32_t*)&pChi[o1] = ph.u; *(uint32_t*)&pClo[o1] = pl.u;
            } else {
                *(float2*)&pCf[o0] = make_float2(v0, v1);
                *(float2*)&pCf[o1] = make_float2(v2, v3);
            }
        }
    }
}

// ---------------- conversions ----------------
__global__ void convert_hs_kernel(const float* __restrict__ hs) {
    const size_t i = ((size_t)blockIdx.x * 256 + threadIdx.x) * 8;
    const int row = (int)(i >> 10);
    if ((row & 2047) >= g_len[row >> 11]) return;   // rows never consumed
    float4 a = *(const float4*)(hs + i);
    float4 b = *(const float4*)(hs + i + 4);
    union { uint4 q; __nv_bfloat16 v[8]; } hi, lo;
    split2(a.x, hi.v[0], lo.v[0]); split2(a.y, hi.v[1], lo.v[1]);
    split2(a.z, hi.v[2], lo.v[2]); split2(a.w, hi.v[3], lo.v[3]);
    split2(b.x, hi.v[4], lo.v[4]); split2(b.y, hi.v[5], lo.v[5]);
    split2(b.z, hi.v[6], lo.v[6]); split2(b.w, hi.v[7], lo.v[7]);
    *(uint4*)&g_hs_hi[i] = hi.q;
    *(uint4*)&g_hs_lo[i] = lo.q;
}

// W [Hq, Dq] fp32 -> Wt [Dq, Hq] hi/lo bf16
__global__ void convert_wT_kernel(const float* __restrict__ W,
                                  __nv_bfloat16* __restrict__ Th, __nv_bfloat16* __restrict__ Tl) {
    __shared__ float t[32][33];
    const int nx = blockIdx.x * 32, ky = blockIdx.y * 32;
    const int x = threadIdx.x, y = threadIdx.y;
#pragma unroll
    for (int i = 0; i < 32; i += 8)
        t[y + i][x] = W[(size_t)(ky + y + i) * Dq + nx + x];
    __syncthreads();
#pragma unroll
    for (int i = 0; i < 32; i += 8) {
        __nv_bfloat16 h, l; split2(t[x][y + i], h, l);
        const size_t o = (size_t)(nx + y + i) * Hq + ky + x;
        Th[o] = h; Tl[o] = l;
    }
}

// g_hw1 [(b*S+t), n] fp32 -> g_hw1t [b][n][t] hi/lo bf16
__global__ void transpose_hw1_kernel() {
    __shared__ float t[32][33];
    const int b = blockIdx.z;
    const int nx = blockIdx.x * 32, sy = blockIdx.y * 32;
    const int x = threadIdx.x, y = threadIdx.y;
#pragma unroll
    for (int i = 0; i < 32; i += 8)
        t[y + i][x] = g_hw1[(size_t)(b * Sq + sy + y + i) * Dq + nx + x];
    __syncthreads();
#pragma unroll
    for (int i = 0; i < 32; i += 8) {
        __nv_bfloat16 h, l; split2(t[x][y + i], h, l);
        const size_t o = (size_t)(b * Dq + nx + y + i) * Sq + sy + x;
        g_hw1t_hi[o] = h; g_hw1t_lo[o] = l;
    }
}

// ---------------- non-GEMM kernels ----------------
__global__ void lens_kernel(const int* __restrict__ mask) {
    __shared__ int red[256];
    const int b = blockIdx.x, tid = threadIdx.x;
    int s = 0;
    for (int t = tid; t < Sq; t += 256) s += mask[b * Sq + t];
    red[tid] = s; __syncthreads();
    for (int w = 128; w > 0; w >>= 1) { if (tid < w) red[tid] += red[tid + w]; __syncthreads(); }
    if (tid == 0) g_len[b] = red[0];
}

__global__ void softmax_scores_kernel() {
    __shared__ float buf[Sq];
    __shared__ float red[256];
    const int row = blockIdx.x;
    const int len = g_len[row >> 11];
    const float* x = g_scores + (size_t)row * Sq;
    const int tid = threadIdx.x;

    float m = -1e30f;
    for (int t = tid; t < Sq; t += 256) { float v = x[t]; buf[t] = v; if (t < len) m = fmaxf(m, v); }
    red[tid] = m; __syncthreads();
    for (int w = 128; w > 0; w >>= 1) { if (tid < w) red[tid] = fmaxf(red[tid], red[tid + w]); __syncthreads(); }
    m = red[0]; __syncthreads();

    float s = 0.f;
    for (int t = tid; t < len; t += 256) { float e = expf(buf[t] - m); buf[t] = e; s += e; }
    red[tid] = s; __syncthreads();
    for (int w = 128; w > 0; w >>= 1) { if (tid < w) red[tid] += red[tid + w]; __syncthreads(); }
    const float Z = red[0];

    for (int t = tid; t < Sq; t += 256) {
        const float p = (t < len) ? buf[t] / Z : 0.f;
        __nv_bfloat16 h, l; split2(p, h, l);
        g_p_hi[(size_t)row * Sq + t] = h;
        g_p_lo[(size_t)row * Sq + t] = l;
    }
}

__global__ void ln_score_kernel(const float* __restrict__ b1,
                                const float* __restrict__ lng, const float* __restrict__ lnb,
                                const float* __restrict__ W2,  const float* __restrict__ b2,
                                float* __restrict__ ts_out)
{
    __shared__ float red[128];
    const int row = blockIdx.x;
    const int tid = threadIdx.x;
    const int b = row >> 11, sIdx = row & (Sq - 1);
    if (sIdx >= g_len[b]) { if (tid == 0) ts_out[row] = -10000.f; return; }
    const float* h = g_h + (size_t)row * Dq;

    float v[4];
    float s = 0.f;
#pragma unroll
    for (int i = 0; i < 4; i++) { v[i] = h[tid + i * 128] + b1[tid + i * 128]; s += v[i]; }
    red[tid] = s; __syncthreads();
    for (int w = 64; w > 0; w >>= 1) { if (tid < w) red[tid] += red[tid + w]; __syncthreads(); }
    const float mu = red[0] / (float)Dq;
    __syncthreads();

    s = 0.f;
#pragma unroll
    for (int i = 0; i < 4; i++) { float d = v[i] - mu; s += d * d; }
    red[tid] = s; __syncthreads();
    for (int w = 64; w > 0; w >>= 1) { if (tid < w) red[tid] += red[tid + w]; __syncthreads(); }
    const float rstd = rsqrtf(red[0] / (float)Dq + 1e-5f);
    __syncthreads();

    s = 0.f;
#pragma unroll
    for (int i = 0; i < 4; i++) {
        const int d = tid + i * 128;
        float y = (v[i] - mu) * rstd * lng[d] + lnb[d];
        y = fmaxf(y, 0.f);
        s += y * W2[d];
    }
    red[tid] = s; __syncthreads();
    for (int w = 64; w > 0; w >>= 1) { if (tid < w) red[tid] += red[tid + w]; __syncthreads(); }
    if (tid == 0) ts_out[row] = red[0] + b2[0];
}

__global__ void rationale_kernel(const float* __restrict__ ts_all, float* __restrict__ rat_out)
{
    __shared__ float cum[Sq];
    __shared__ float rv[256];
    __shared__ int   ri[256];
    const int b = blockIdx.x, tid = threadIdx.x;
    const float* ts = ts_all + b * Sq;

    for (int t = tid; t < Sq; t += 256) cum[t] = ts[t];
    __syncthreads();
    if (tid == 0) { float a = 0.f; for (int t = 0; t < Sq; t++) { a += cum[t]; cum[t] = a; } }
    __syncthreads();

    const int vl = g_len[b];
    float best = -1e38f; int bi = 1 << 30;
    for (int idx = tid; idx < 18 * Sq; idx += 256) {
        const int Li = idx >> 11;
        const int s  = idx & (Sq - 1);
        const int L  = 3 + Li;
        if (L <= vl && s <= vl - L) {
            int e = s + L - 1; if (e > Sq - 1) e = Sq - 1;
            const float val = cum[e] / (float)L + 0.01f * ((float)L / 20.0f);
            if (val > best || (val == best && idx < bi)) { best = val; bi = idx; }
        }
    }
    rv[tid] = best; ri[tid] = bi; __syncthreads();
    for (int w = 128; w > 0; w >>= 1) {
        if (tid < w) {
            if (rv[tid + w] > rv[tid] || (rv[tid + w] == rv[tid] && ri[tid + w] < ri[tid])) {
                rv[tid] = rv[tid + w]; ri[tid] = ri[tid + w];
            }
        }
        __syncthreads();
    }
    int idx = ri[0];
    if (idx >= 18 * Sq) idx = 0;
    const int bestL = 3 + (idx >> 11);
    const int bests = idx & (Sq - 1);
    const bool shortc = (vl <= 3);

    for (int t = tid; t < Sq; t += 256) {
        const float r = shortc ? ((t < vl) ? 1.f : 0.f)
                               : ((t >= bests && t < bests + bestL) ? 1.f : 0.f);
        rat_out[b * Sq + t] = r;
    }
    if (tid == 0) g_ratlen[b] = shortc ? (float)vl : (float)bestL;
}

__global__ void token_probs_kernel(const float* __restrict__ ts, float* __restrict__ tp)
{
    __shared__ float buf[Sq];
    __shared__ float red[256];
    const int b = blockIdx.x, tid = threadIdx.x;
    const float* x = ts + b * Sq;

    float m = -1e30f;
    for (int t = tid; t < Sq; t += 256) { float v = x[t]; buf[t] = v; m = fmaxf(m, v); }
    red[tid] = m; __syncthreads();
    for (int w = 128; w > 0; w >>= 1) { if (tid < w) red[tid] = fmaxf(red[tid], red[tid + w]); __syncthreads(); }
    m = red[0]; __syncthreads();

    float s = 0.f;
    for (int t = tid; t < Sq; t += 256) { float e = expf(buf[t] - m); buf[t] = e; s += e; }
    red[tid] = s; __syncthreads();
    for (int w = 128; w > 0; w >>= 1) { if (tid < w) red[tid] += red[tid + w]; __syncthreads(); }
    const float Z = red[0];

    for (int t = tid; t < Sq; t += 256) tp[b * Sq + t] = buf[t] / Z;
}

__global__ void attended_pooled_kernel(const float* __restrict__ hs,
                                       const float* __restrict__ rat,
                                       float* __restrict__ att, float* __restrict__ pooled)
{
    __shared__ float r[Sq];
    const int b = blockIdx.y;
    const int h = blockIdx.x * 256 + threadIdx.x;
    for (int t = threadIdx.x; t < Sq; t += 256) r[t] = rat[b * Sq + t];
    __syncthreads();

    const float* hsb = hs  + (size_t)b * Sq * Hq;
    float*      attb = att + (size_t)b * Sq * Hq;
    float a0 = 0.f, a1 = 0.f, a2 = 0.f, a3 = 0.f;
    for (int s = 0; s < Sq; s += 4) {
        float v0 = (r[s+0] != 0.f) ? hsb[(size_t)(s+0) * Hq + h] * r[s+0] : 0.f;
        float v1 = (r[s+1] != 0.f) ? hsb[(size_t)(s+1) * Hq + h] * r[s+1] : 0.f;
        float v2 = (r[s+2] != 0.f) ? hsb[(size_t)(s+2) * Hq + h] * r[s+2] : 0.f;
        float v3 = (r[s+3] != 0.f) ? hsb[(size_t)(s+3) * Hq + h] * r[s+3] : 0.f;
        attb[(size_t)(s+0) * Hq + h] = v0;
        attb[(size_t)(s+1) * Hq + h] = v1;
        attb[(size_t)(s+2) * Hq + h] = v2;
        attb[(size_t)(s+3) * Hq + h] = v3;
        a0 += v0; a1 += v1; a2 += v2; a3 += v3;
    }
    pooled[b * Hq + h] = ((a0 + a1) + (a2 + a3)) / (g_ratlen[b] + 1e-6f);
}

// ---------------------------------------------------------------------------
extern "C" void kernel_launch(void* const* d_in, const int* in_sizes, int n_in,
                              void* d_out, int out_size)
{
    (void)in_sizes; (void)n_in; (void)out_size;
    const float* hs  = (const float*)d_in[0];
    const int*   am  = (const int*)  d_in[1];
    const float* Wq  = (const float*)d_in[2];
    const float* bq  = (const float*)d_in[3];
    const float* Wk  = (const float*)d_in[4];
    const float* bk  = (const float*)d_in[5];
    const float* W1  = (const float*)d_in[6];
    const float* b1  = (const float*)d_in[7];
    const float* lng = (const float*)d_in[8];
    const float* lnb = (const float*)d_in[9];
    const float* W2  = (const float*)d_in[10];
    const float* b2  = (const float*)d_in[11];

    float* out    = (float*)d_out;
    float* ts     = out;
    float* rat    = out + (size_t)MSq;
    float* tp     = out + (size_t)2 * MSq;
    float* att    = out + (size_t)3 * MSq;
    float* pooled = out + (size_t)3 * MSq + (size_t)MSq * Hq;

    __nv_bfloat16 *hsh, *hsl, *wqh, *wql, *wkh, *wkl, *w1h, *w1l;
    __nv_bfloat16 *qh, *ql, *kh, *kl, *h1th, *h1tl, *ph, *pl;
    float *hw1, *sc, *hbuf;
    cudaGetSymbolAddress((void**)&hsh, g_hs_hi);  cudaGetSymbolAddress((void**)&hsl, g_hs_lo);
    cudaGetSymbolAddress((void**)&wqh, g_wqT_hi); cudaGetSymbolAddress((void**)&wql, g_wqT_lo);
    cudaGetSymbolAddress((void**)&wkh, g_wkT_hi); cudaGetSymbolAddress((void**)&wkl, g_wkT_lo);
    cudaGetSymbolAddress((void**)&w1h, g_w1T_hi); cudaGetSymbolAddress((void**)&w1l, g_w1T_lo);
    cudaGetSymbolAddress((void**)&qh,  g_q_hi);   cudaGetSymbolAddress((void**)&ql,  g_q_lo);
    cudaGetSymbolAddress((void**)&kh,  g_k_hi);   cudaGetSymbolAddress((void**)&kl,  g_k_lo);
    cudaGetSymbolAddress((void**)&h1th, g_hw1t_hi); cudaGetSymbolAddress((void**)&h1tl, g_hw1t_lo);
    cudaGetSymbolAddress((void**)&ph,  g_p_hi);   cudaGetSymbolAddress((void**)&pl,  g_p_lo);
    cudaGetSymbolAddress((void**)&hw1, g_hw1);
    cudaGetSymbolAddress((void**)&sc,  g_scores);
    cudaGetSymbolAddress((void**)&hbuf, g_h);

    cudaFuncSetAttribute(mma_gemm<0>, cudaFuncAttributeMaxDynamicSharedMemorySize, MM_SMEM);
    cudaFuncSetAttribute(mma_gemm<1>, cudaFuncAttributeMaxDynamicSharedMemorySize, MM_SMEM);
    cudaFuncSetAttribute(mma_gemm<2>, cudaFuncAttributeMaxDynamicSharedMemorySize, MM_SMEM);
    cudaFuncSetAttribute(mma_gemm<3>, cudaFuncAttributeMaxDynamicSharedMemorySize, MM_SMEM);

    lens_kernel<<<Bq, 256>>>(am);
    convert_hs_kernel<<<(int)(((size_t)MSq * Hq) / 8 / 256), 256>>>(hs);
    dim3 wg(Dq / 32, Hq / 32);
    convert_wT_kernel<<<wg, dim3(32, 8)>>>(Wq, wqh, wql);
    convert_wT_kernel<<<wg, dim3(32, 8)>>>(Wk, wkh, wkl);
    convert_wT_kernel<<<wg, dim3(32, 8)>>>(W1, w1h, w1l);

    // projections: M=32768, N=512, K=1024 (row-blocks >= len[b] skipped)
    dim3 gP(Dq / 128, MSq / 128, 1);
    mma_gemm<0><<<gP, 256, MM_SMEM>>>(hsh, hsl, wqh, wql, bq, 1.f,
        nullptr, qh, ql, Hq, Dq, 0, 0, 0);
    mma_gemm<0><<<gP, 256, MM_SMEM>>>(hsh, hsl, wkh, wkl, bk, 1.f,
        nullptr, kh, kl, Hq, Dq, 0, 0, 0);
    mma_gemm<1><<<gP, 256, MM_SMEM>>>(hsh, hsl, w1h, w1l, nullptr, 1.f,
        hw1, nullptr, nullptr, Hq, Dq, 0, 0, 0);

    // scores = Q @ K^T / sqrt(D): per batch 2048x2048, K=512 (skip dead blocks)
    dim3 gS(Sq / 128, Sq / 128, Bq);
    mma_gemm<2><<<gS, 256, MM_SMEM>>>(qh, ql, kh, kl, nullptr,
        0.044194173824159216f, sc, nullptr, nullptr, Dq, Sq,
        (long long)Sq * Dq, (long long)Sq * Dq, (long long)Sq * Sq);

    transpose_hw1_kernel<<<dim3(Dq / 32, Sq / 32, Bq), dim3(32, 8)>>>();
    softmax_scores_kernel<<<MSq, 256>>>();

    // h = probs @ HSW1: per batch 2048x512, K=2048 clamped to len
    dim3 gH(Dq / 128, Sq / 128, Bq);
    mma_gemm<3><<<gH, 256, MM_SMEM>>>(ph, pl, h1th, h1tl, nullptr, 1.f,
        hbuf, nullptr, nullptr, Sq, Dq,
        (long long)Sq * Sq, (long long)Dq * Sq, (long long)Sq * Dq);

    ln_score_kernel<<<MSq, 128>>>(b1, lng, lnb, W2, b2, ts);
    rationale_kernel<<<Bq, 256>>>(ts, rat);
    token_probs_kernel<<<Bq, 256>>>(ts, tp);
    attended_pooled_kernel<<<dim3(Hq / 256, Bq), 256>>>(hs, rat, att, pooled);
}

// round 6
// speedup vs baseline: 1.5641x; 1.0315x over previous
#include <cuda_runtime.h>
#include <cuda_bf16.h>
#include <math.h>
#include <stdint.h>

#define Bq 16
#define Sq 2048
#define Hq 1024
#define Dq 512
#define MSq (Bq * Sq)   // 32768

// ---------------- scratch (__device__ globals; no allocations) ----------------
__device__ __nv_bfloat16 g_hs_hi[(size_t)MSq * Hq];
__device__ __nv_bfloat16 g_hs_lo[(size_t)MSq * Hq];
__device__ __nv_bfloat16 g_wqT_hi[(size_t)Dq * Hq];
__device__ __nv_bfloat16 g_wqT_lo[(size_t)Dq * Hq];
__device__ __nv_bfloat16 g_wkT_hi[(size_t)Dq * Hq];
__device__ __nv_bfloat16 g_wkT_lo[(size_t)Dq * Hq];
__device__ __nv_bfloat16 g_w1T_hi[(size_t)Dq * Hq];
__device__ __nv_bfloat16 g_w1T_lo[(size_t)Dq * Hq];
__device__ __nv_bfloat16 g_q_hi[(size_t)MSq * Dq];
__device__ __nv_bfloat16 g_q_lo[(size_t)MSq * Dq];
__device__ __nv_bfloat16 g_k_hi[(size_t)MSq * Dq];
__device__ __nv_bfloat16 g_k_lo[(size_t)MSq * Dq];
__device__ float         g_hw1[(size_t)MSq * Dq];                 // fp32, [B*S, D]
__device__ __nv_bfloat16 g_hw1t_hi[(size_t)Bq * Dq * Sq];         // [b][n][t]
__device__ __nv_bfloat16 g_hw1t_lo[(size_t)Bq * Dq * Sq];
__device__ float         g_scores[(size_t)Bq * Sq * Sq];          // 256 MB
__device__ __nv_bfloat16 g_p_hi[(size_t)Bq * Sq * Sq];
__device__ __nv_bfloat16 g_p_lo[(size_t)Bq * Sq * Sq];
__device__ float         g_h[(size_t)MSq * Dq];
__device__ int           g_len[Bq];
__device__ float         g_ratlen[Bq];
__device__ int           g_spanstart[Bq];
__device__ int           g_spanlen[Bq];

// ---------------- helpers ----------------
__device__ __forceinline__ uint32_t smem_u32(const void* p) {
    uint32_t a;
    asm("{ .reg .u64 t; cvta.to.shared.u64 t, %1; cvt.u32.u64 %0, t; }" : "=r"(a) : "l"(p));
    return a;
}
__device__ __forceinline__ void cpa16(uint32_t s, const void* g) {
    asm volatile("cp.async.cg.shared.global [%0], [%1], 16;" :: "r"(s), "l"(g));
}
__device__ __forceinline__ void cpa_commit() {
    asm volatile("cp.async.commit_group;" ::: "memory");
}
template<int N> __device__ __forceinline__ void cpa_wait() {
    asm volatile("cp.async.wait_group %0;" :: "n"(N) : "memory");
}
__device__ __forceinline__ void ldm4(uint32_t* d, uint32_t a) {
    asm volatile("ldmatrix.sync.aligned.m8n8.x4.shared.b16 {%0,%1,%2,%3}, [%4];"
        : "=r"(d[0]), "=r"(d[1]), "=r"(d[2]), "=r"(d[3]) : "r"(a));
}
__device__ __forceinline__ void mma16816(float* c, const uint32_t* a, const uint32_t* b) {
    asm volatile("mma.sync.aligned.m16n8k16.row.col.f32.bf16.bf16.f32 "
        "{%0,%1,%2,%3}, {%4,%5,%6,%7}, {%8,%9}, {%0,%1,%2,%3};"
        : "+f"(c[0]), "+f"(c[1]), "+f"(c[2]), "+f"(c[3])
        : "r"(a[0]), "r"(a[1]), "r"(a[2]), "r"(a[3]), "r"(b[0]), "r"(b[1]));
}
__device__ __forceinline__ void split2(float v, __nv_bfloat16& h, __nv_bfloat16& l) {
    h = __float2bfloat16(v);
    l = __float2bfloat16(v - __bfloat162float(h));
}
// SW128-style swizzle inside a 128-byte row: chunk' = chunk ^ (row & 7)
__device__ __forceinline__ uint32_t swz(int r, int chunk) {
    return ((uint32_t)r << 7) + (uint32_t)((chunk ^ (r & 7)) << 4);
}

// ---------------------------------------------------------------------------
// Split-bf16 mma.sync GEMM (round-3 engine: 128x128 tile, K-chunk 64,
// 2-stage cp.async double buffer, 8 warps 64x32 each).
// MODE 0: projection, SPLIT bf16 out + bias; skip row-blocks >= len[b]
// MODE 1: projection, f32 out (hw1);        skip row-blocks >= len[b]
// MODE 2: scores, f32 out, alpha;           skip m0>=len[z] || n0>=len[z]
// MODE 3: probs GEMM, f32 out;              skip m0>=len[z], clamp K to len
// ---------------------------------------------------------------------------
#define MM_SMEM 131072

template<int MODE>
__global__ void __launch_bounds__(256)
mma_gemm(const __nv_bfloat16* __restrict__ Ah, const __nv_bfloat16* __restrict__ Al,
         const __nv_bfloat16* __restrict__ Bh, const __nv_bfloat16* __restrict__ Bl,
         const float* __restrict__ bias, float alpha,
         float* __restrict__ Cf, __nv_bfloat16* __restrict__ Chi, __nv_bfloat16* __restrict__ Clo,
         int K, int ldc, long long sA, long long sB, long long sC)
{
    extern __shared__ char dsm[];
    const uint32_t sb0 = smem_u32(dsm);
    const int tid  = threadIdx.x;
    const int lane = tid & 31;
    const int wid  = tid >> 5;
    const int wm   = wid & 1;
    const int wn   = wid >> 1;

    const long long z = blockIdx.z;
    const int m0 = blockIdx.y * 128;
    const int n0 = blockIdx.x * 128;

    int NK = K >> 6;
    if (MODE == 0 || MODE == 1) {
        if ((m0 & 2047) >= g_len[m0 >> 11]) return;
    } else if (MODE == 2) {
        const int len = g_len[z];
        if (m0 >= len || n0 >= len) return;
    } else {
        const int len = g_len[z];
        if (m0 >= len) return;
        const int nk2 = (len + 63) >> 6;
        if (nk2 < NK) NK = nk2;
    }

    const __nv_bfloat16* pAh = Ah + z * sA;
    const __nv_bfloat16* pAl = Al + z * sA;
    const __nv_bfloat16* pBh = Bh + z * sB;
    const __nv_bfloat16* pBl = Bl + z * sB;

    // cp.async issue for one K-chunk into stage (kt&1)
    const int r_ld  = tid >> 1;
    const int cu_ld = (tid & 1) << 2;
    const long long arow = (long long)(m0 + r_ld) * K;
    const long long brow = (long long)(n0 + r_ld) * K;

    auto issue = [&](int kt) {
        const uint32_t so = sb0 + ((uint32_t)(kt & 1) << 16);
        const int k0 = kt << 6;
#pragma unroll
        for (int i = 0; i < 4; i++) {
            const int ch = cu_ld + i;
            const uint32_t sw = swz(r_ld, ch);
            const int go = k0 + ch * 8;
            cpa16(so +     0 + sw, pAh + arow + go);
            cpa16(so + 16384 + sw, pAl + arow + go);
            cpa16(so + 32768 + sw, pBh + brow + go);
            cpa16(so + 49152 + sw, pBl + brow + go);
        }
        cpa_commit();
    };

    float acc[4][4][4];
#pragma unroll
    for (int i = 0; i < 4; i++)
#pragma unroll
        for (int j = 0; j < 4; j++)
#pragma unroll
            for (int e = 0; e < 4; e++) acc[i][j][e] = 0.f;

    const int l15 = lane & 15, lhi = lane >> 4;
    int rA[4], rB[2];
#pragma unroll
    for (int mi = 0; mi < 4; mi++) rA[mi] = wm * 64 + mi * 16 + l15;
#pragma unroll
    for (int bj = 0; bj < 2; bj++) rB[bj] = wn * 32 + bj * 16 + l15;

    issue(0);

#pragma unroll 1
    for (int kt = 0; kt < NK; kt++) {
        if (kt + 1 < NK) { issue(kt + 1); cpa_wait<1>(); }
        else             { cpa_wait<0>(); }
        __syncthreads();

        const uint32_t uA = sb0 + ((uint32_t)(kt & 1) << 16);
        const uint32_t uAl = uA + 16384, uBh = uA + 32768, uBl = uA + 49152;

#pragma unroll
        for (int ks = 0; ks < 4; ks++) {
            const int ch = ks * 2 + lhi;
            uint32_t ah[4][4], al[4][4], bh[4][2], bl[4][2];
#pragma unroll
            for (int mi = 0; mi < 4; mi++) ldm4(ah[mi], uA  + swz(rA[mi], ch));
#pragma unroll
            for (int mi = 0; mi < 4; mi++) ldm4(al[mi], uAl + swz(rA[mi], ch));
#pragma unroll
            for (int bj = 0; bj < 2; bj++) {
                uint32_t q[4];
                ldm4(q, uBh + swz(rB[bj], ch));
                bh[bj*2][0] = q[0]; bh[bj*2+1][0] = q[1];
                bh[bj*2][1] = q[2]; bh[bj*2+1][1] = q[3];
                ldm4(q, uBl + swz(rB[bj], ch));
                bl[bj*2][0] = q[0]; bl[bj*2+1][0] = q[1];
                bl[bj*2][1] = q[2]; bl[bj*2+1][1] = q[3];
            }
#pragma unroll
            for (int mi = 0; mi < 4; mi++)
#pragma unroll
                for (int nj = 0; nj < 4; nj++) {
                    mma16816(acc[mi][nj], ah[mi], bh[nj]);
                    mma16816(acc[mi][nj], ah[mi], bl[nj]);
                    mma16816(acc[mi][nj], al[mi], bh[nj]);
                }
        }
        __syncthreads();
    }

    // ---- epilogue: direct gmem stores from fragments ----
    float*         pCf  = Cf  + z * sC;
    __nv_bfloat16* pChi = Chi + z * sC;
    __nv_bfloat16* pClo = Clo + z * sC;
    const int r4 = lane >> 2, c2 = (lane & 3) << 1;
#pragma unroll
    for (int mi = 0; mi < 4; mi++) {
        const long long gm = (long long)(m0 + wm * 64 + mi * 16 + r4);
#pragma unroll
        for (int nj = 0; nj < 4; nj++) {
            const int gn = n0 + wn * 32 + nj * 8 + c2;
            float v0 = alpha * acc[mi][nj][0];
            float v1 = alpha * acc[mi][nj][1];
            float v2 = alpha * acc[mi][nj][2];
            float v3 = alpha * acc[mi][nj][3];
            if (MODE == 0) {
                const float bx = bias[gn], by = bias[gn + 1];
                v0 += bx; v1 += by; v2 += bx; v3 += by;
            }
            const long long o0 = gm * ldc + gn;
            const long long o1 = (gm + 8) * ldc + gn;
            if (MODE == 0) {
                union { __nv_bfloat16 b[2]; uint32_t u; } ph, pl;
                __nv_bfloat16 h0,l0,h1,l1;
                split2(v0,h0,l0); split2(v1,h1,l1);
                ph.b[0]=h0; ph.b[1]=h1; pl.b[0]=l0; pl.b[1]=l1;
                *(uint32_t*)&pChi[o0] = ph.u; *(uint32_t*)&pClo[o0] = pl.u;
                split2(v2,h0,l0); split2(v3,h1,l1);
                ph.b[0]=h0; ph.b[1]=h1; pl.b[0]=l0; pl.b[1]=l1;
                *(uint32_t*)&pChi[o1] = ph.u; *(uint32_t*)&pClo[o1] = pl.u;
            } else {
                *(float2*)&pCf[o0] = make_float2(v0, v1);
                *(float2*)&pCf[o1] = make_float2(v2, v3);
            }
        }
    }
}

// ---------------- conversions ----------------
__global__ void convert_hs_kernel(const float* __restrict__ hs) {
    const size_t i = ((size_t)blockIdx.x * 256 + threadIdx.x) * 8;
    const int row = (int)(i >> 10);
    if ((row & 2047) >= g_len[row >> 11]) return;   // rows never consumed
    float4 a = *(const float4*)(hs + i);
    float4 b = *(const float4*)(hs + i + 4);
    union { uint4 q; __nv_bfloat16 v[8]; } hi, lo;
    split2(a.x, hi.v[0], lo.v[0]); split2(a.y, hi.v[1], lo.v[1]);
    split2(a.z, hi.v[2], lo.v[2]); split2(a.w, hi.v[3], lo.v[3]);
    split2(b.x, hi.v[4], lo.v[4]); split2(b.y, hi.v[5], lo.v[5]);
    split2(b.z, hi.v[6], lo.v[6]); split2(b.w, hi.v[7], lo.v[7]);
    *(uint4*)&g_hs_hi[i] = hi.q;
    *(uint4*)&g_hs_lo[i] = lo.q;
}

// W [Hq, Dq] fp32 -> Wt [Dq, Hq] hi/lo bf16
__global__ void convert_wT_kernel(const float* __restrict__ W,
                                  __nv_bfloat16* __restrict__ Th, __nv_bfloat16* __restrict__ Tl) {
    __shared__ float t[32][33];
    const int nx = blockIdx.x * 32, ky = blockIdx.y * 32;
    const int x = threadIdx.x, y = threadIdx.y;
#pragma unroll
    for (int i = 0; i < 32; i += 8)
        t[y + i][x] = W[(size_t)(ky + y + i) * Dq + nx + x];
    __syncthreads();
#pragma unroll
    for (int i = 0; i < 32; i += 8) {
        __nv_bfloat16 h, l; split2(t[x][y + i], h, l);
        const size_t o = (size_t)(nx + y + i) * Hq + ky + x;
        Th[o] = h; Tl[o] = l;
    }
}

// g_hw1 [(b*S+t), n] fp32 -> g_hw1t [b][n][t] hi/lo bf16
// Skip t-tiles >= roundup64(len): the probs GEMM clamps K and never reads them.
__global__ void transpose_hw1_kernel() {
    __shared__ float t[32][33];
    const int b = blockIdx.z;
    const int nx = blockIdx.x * 32, sy = blockIdx.y * 32;
    const int nk64 = (g_len[b] + 63) & ~63;
    if (sy >= nk64) return;
    const int x = threadIdx.x, y = threadIdx.y;
#pragma unroll
    for (int i = 0; i < 32; i += 8)
        t[y + i][x] = g_hw1[(size_t)(b * Sq + sy + y + i) * Dq + nx + x];
    __syncthreads();
#pragma unroll
    for (int i = 0; i < 32; i += 8) {
        __nv_bfloat16 h, l; split2(t[x][y + i], h, l);
        const size_t o = (size_t)(b * Dq + nx + y + i) * Sq + sy + x;
        g_hw1t_hi[o] = h; g_hw1t_lo[o] = l;
    }
}

// ---------------- non-GEMM kernels ----------------
__global__ void lens_kernel(const int* __restrict__ mask) {
    __shared__ int red[256];
    const int b = blockIdx.x, tid = threadIdx.x;
    int s = 0;
    for (int t = tid; t < Sq; t += 256) s += mask[b * Sq + t];
    red[tid] = s; __syncthreads();
    for (int w = 128; w > 0; w >>= 1) { if (tid < w) red[tid] += red[tid + w]; __syncthreads(); }
    if (tid == 0) g_len[b] = red[0];
}

// Rows >= len skipped (p stays zero-init; only ever hit by clamped-K GEMM).
// Reads/writes bounded by len / roundup64(len).
__global__ void softmax_scores_kernel() {
    __shared__ float buf[Sq];
    __shared__ float red[256];
    const int row = blockIdx.x;
    const int len = g_len[row >> 11];
    if ((row & 2047) >= len) return;
    const int nk64 = (len + 63) & ~63;
    const float* x = g_scores + (size_t)row * Sq;
    const int tid = threadIdx.x;

    float m = -1e30f;
    for (int t = tid; t < len; t += 256) { float v = x[t]; buf[t] = v; m = fmaxf(m, v); }
    red[tid] = m; __syncthreads();
    for (int w = 128; w > 0; w >>= 1) { if (tid < w) red[tid] = fmaxf(red[tid], red[tid + w]); __syncthreads(); }
    m = red[0]; __syncthreads();

    float s = 0.f;
    for (int t = tid; t < len; t += 256) { float e = expf(buf[t] - m); buf[t] = e; s += e; }
    red[tid] = s; __syncthreads();
    for (int w = 128; w > 0; w >>= 1) { if (tid < w) red[tid] += red[tid + w]; __syncthreads(); }
    const float Z = red[0];

    for (int t = tid; t < nk64; t += 256) {
        const float p = (t < len) ? buf[t] / Z : 0.f;
        __nv_bfloat16 h, l; split2(p, h, l);
        g_p_hi[(size_t)row * Sq + t] = h;
        g_p_lo[(size_t)row * Sq + t] = l;
    }
}

__global__ void ln_score_kernel(const float* __restrict__ b1,
                                const float* __restrict__ lng, const float* __restrict__ lnb,
                                const float* __restrict__ W2,  const float* __restrict__ b2,
                                float* __restrict__ ts_out)
{
    __shared__ float red[128];
    const int row = blockIdx.x;
    const int tid = threadIdx.x;
    const int b = row >> 11, sIdx = row & (Sq - 1);
    if (sIdx >= g_len[b]) { if (tid == 0) ts_out[row] = -10000.f; return; }
    const float* h = g_h + (size_t)row * Dq;

    float v[4];
    float s = 0.f;
#pragma unroll
    for (int i = 0; i < 4; i++) { v[i] = h[tid + i * 128] + b1[tid + i * 128]; s += v[i]; }
    red[tid] = s; __syncthreads();
    for (int w = 64; w > 0; w >>= 1) { if (tid < w) red[tid] += red[tid + w]; __syncthreads(); }
    const float mu = red[0] / (float)Dq;
    __syncthreads();

    s = 0.f;
#pragma unroll
    for (int i = 0; i < 4; i++) { float d = v[i] - mu; s += d * d; }
    red[tid] = s; __syncthreads();
    for (int w = 64; w > 0; w >>= 1) { if (tid < w) red[tid] += red[tid + w]; __syncthreads(); }
    const float rstd = rsqrtf(red[0] / (float)Dq + 1e-5f);
    __syncthreads();

    s = 0.f;
#pragma unroll
    for (int i = 0; i < 4; i++) {
        const int d = tid + i * 128;
        float y = (v[i] - mu) * rstd * lng[d] + lnb[d];
        y = fmaxf(y, 0.f);
        s += y * W2[d];
    }
    red[tid] = s; __syncthreads();
    for (int w = 64; w > 0; w >>= 1) { if (tid < w) red[tid] += red[tid + w]; __syncthreads(); }
    if (tid == 0) ts_out[row] = red[0] + b2[0];
}

__global__ void rationale_kernel(const float* __restrict__ ts_all, float* __restrict__ rat_out)
{
    __shared__ float cum[Sq];
    __shared__ float rv[256];
    __shared__ int   ri[256];
    const int b = blockIdx.x, tid = threadIdx.x;
    const float* ts = ts_all + b * Sq;

    for (int t = tid; t < Sq; t += 256) cum[t] = ts[t];
    __syncthreads();
    if (tid == 0) { float a = 0.f; for (int t = 0; t < Sq; t++) { a += cum[t]; cum[t] = a; } }
    __syncthreads();

    const int vl = g_len[b];
    float best = -1e38f; int bi = 1 << 30;
    for (int idx = tid; idx < 18 * Sq; idx += 256) {
        const int Li = idx >> 11;
        const int s  = idx & (Sq - 1);
        const int L  = 3 + Li;
        if (L <= vl && s <= vl - L) {
            int e = s + L - 1; if (e > Sq - 1) e = Sq - 1;
            const float val = cum[e] / (float)L + 0.01f * ((float)L / 20.0f);
            if (val > best || (val == best && idx < bi)) { best = val; bi = idx; }
        }
    }
    rv[tid] = best; ri[tid] = bi; __syncthreads();
    for (int w = 128; w > 0; w >>= 1) {
        if (tid < w) {
            if (rv[tid + w] > rv[tid] || (rv[tid + w] == rv[tid] && ri[tid + w] < ri[tid])) {
                rv[tid] = rv[tid + w]; ri[tid] = ri[tid + w];
            }
        }
        __syncthreads();
    }
    int idx = ri[0];
    if (idx >= 18 * Sq) idx = 0;
    const int bestL = 3 + (idx >> 11);
    const int bests = idx & (Sq - 1);
    const bool shortc = (vl <= 3);

    for (int t = tid; t < Sq; t += 256) {
        const float r = shortc ? ((t < vl) ? 1.f : 0.f)
                               : ((t >= bests && t < bests + bestL) ? 1.f : 0.f);
        rat_out[b * Sq + t] = r;
    }
    if (tid == 0) {
        g_ratlen[b]    = shortc ? (float)vl : (float)bestL;
        g_spanstart[b] = shortc ? 0 : bests;
        g_spanlen[b]   = shortc ? vl : bestL;
    }
}

__global__ void token_probs_kernel(const float* __restrict__ ts, float* __restrict__ tp)
{
    __shared__ float buf[Sq];
    __shared__ float red[256];
    const int b = blockIdx.x, tid = threadIdx.x;
    const float* x = ts + b * Sq;

    float m = -1e30f;
    for (int t = tid; t < Sq; t += 256) { float v = x[t]; buf[t] = v; m = fmaxf(m, v); }
    red[tid] = m; __syncthreads();
    for (int w = 128; w > 0; w >>= 1) { if (tid < w) red[tid] = fmaxf(red[tid], red[tid + w]); __syncthreads(); }
    m = red[0]; __syncthreads();

    float s = 0.f;
    for (int t = tid; t < Sq; t += 256) { float e = expf(buf[t] - m); buf[t] = e; s += e; }
    red[tid] = s; __syncthreads();
    for (int w = 128; w > 0; w >>= 1) { if (tid < w) red[tid] += red[tid + w]; __syncthreads(); }
    const float Z = red[0];

    for (int t = tid; t < Sq; t += 256) tp[b * Sq + t] = buf[t] / Z;
}

// attended = hs inside span, 0 elsewhere (rat values are exactly 1 in span).
// hs read only for span rows (<=2048 worst case, ~20 typical).
__global__ void attended_pooled_kernel(const float* __restrict__ hs,
                                       float* __restrict__ att, float* __restrict__ pooled)
{
    const int b = blockIdx.y;
    const int h = blockIdx.x * 256 + threadIdx.x;
    const int ss = g_spanstart[b];
    const int se = ss + g_spanlen[b];

    const float* hsb = hs  + (size_t)b * Sq * Hq + h;
    float*      attb = att + (size_t)b * Sq * Hq + h;
    float acc = 0.f;
    for (int s = 0; s < ss; s++)  attb[(size_t)s * Hq] = 0.f;
    for (int s = ss; s < se; s++) { float v = hsb[(size_t)s * Hq]; attb[(size_t)s * Hq] = v; acc += v; }
    for (int s = se; s < Sq; s++) attb[(size_t)s * Hq] = 0.f;
    pooled[b * Hq + h] = acc / (g_ratlen[b] + 1e-6f);
}

// ---------------------------------------------------------------------------
extern "C" void kernel_launch(void* const* d_in, const int* in_sizes, int n_in,
                              void* d_out, int out_size)
{
    (void)in_sizes; (void)n_in; (void)out_size;
    const float* hs  = (const float*)d_in[0];
    const int*   am  = (const int*)  d_in[1];
    const float* Wq  = (const float*)d_in[2];
    const float* bq  = (const float*)d_in[3];
    const float* Wk  = (const float*)d_in[4];
    const float* bk  = (const float*)d_in[5];
    const float* W1  = (const float*)d_in[6];
    const float* b1  = (const float*)d_in[7];
    const float* lng = (const float*)d_in[8];
    const float* lnb = (const float*)d_in[9];
    const float* W2  = (const float*)d_in[10];
    const float* b2  = (const float*)d_in[11];

    float* out    = (float*)d_out;
    float* ts     = out;
    float* rat    = out + (size_t)MSq;
    float* tp     = out + (size_t)2 * MSq;
    float* att    = out + (size_t)3 * MSq;
    float* pooled = out + (size_t)3 * MSq + (size_t)MSq * Hq;

    __nv_bfloat16 *hsh, *hsl, *wqh, *wql, *wkh, *wkl, *w1h, *w1l;
    __nv_bfloat16 *qh, *ql, *kh, *kl, *h1th, *h1tl, *ph, *pl;
    float *hw1, *sc, *hbuf;
    cudaGetSymbolAddress((void**)&hsh, g_hs_hi);  cudaGetSymbolAddress((void**)&hsl, g_hs_lo);
    cudaGetSymbolAddress((void**)&wqh, g_wqT_hi); cudaGetSymbolAddress((void**)&wql, g_wqT_lo);
    cudaGetSymbolAddress((void**)&wkh, g_wkT_hi); cudaGetSymbolAddress((void**)&wkl, g_wkT_lo);
    cudaGetSymbolAddress((void**)&w1h, g_w1T_hi); cudaGetSymbolAddress((void**)&w1l, g_w1T_lo);
    cudaGetSymbolAddress((void**)&qh,  g_q_hi);   cudaGetSymbolAddress((void**)&ql,  g_q_lo);
    cudaGetSymbolAddress((void**)&kh,  g_k_hi);   cudaGetSymbolAddress((void**)&kl,  g_k_lo);
    cudaGetSymbolAddress((void**)&h1th, g_hw1t_hi); cudaGetSymbolAddress((void**)&h1tl, g_hw1t_lo);
    cudaGetSymbolAddress((void**)&ph,  g_p_hi);   cudaGetSymbolAddress((void**)&pl,  g_p_lo);
    cudaGetSymbolAddress((void**)&hw1, g_hw1);
    cudaGetSymbolAddress((void**)&sc,  g_scores);
    cudaGetSymbolAddress((void**)&hbuf, g_h);

    cudaFuncSetAttribute(mma_gemm<0>, cudaFuncAttributeMaxDynamicSharedMemorySize, MM_SMEM);
    cudaFuncSetAttribute(mma_gemm<1>, cudaFuncAttributeMaxDynamicSharedMemorySize, MM_SMEM);
    cudaFuncSetAttribute(mma_gemm<2>, cudaFuncAttributeMaxDynamicSharedMemorySize, MM_SMEM);
    cudaFuncSetAttribute(mma_gemm<3>, cudaFuncAttributeMaxDynamicSharedMemorySize, MM_SMEM);

    // launch order chosen so ncu (-s 5 -c 1) lands on the first GEMM
    lens_kernel<<<Bq, 256>>>(am);                                     // 0
    dim3 wg(Dq / 32, Hq / 32);
    convert_wT_kernel<<<wg, dim3(32, 8)>>>(Wq, wqh, wql);             // 1
    convert_wT_kernel<<<wg, dim3(32, 8)>>>(Wk, wkh, wkl);             // 2
    convert_wT_kernel<<<wg, dim3(32, 8)>>>(W1, w1h, w1l);             // 3
    convert_hs_kernel<<<(int)(((size_t)MSq * Hq) / 8 / 256), 256>>>(hs); // 4

    // projections: M=32768, N=512, K=1024 (row-blocks >= len[b] skipped)
    dim3 gP(Dq / 128, MSq / 128, 1);
    mma_gemm<0><<<gP, 256, MM_SMEM>>>(hsh, hsl, wqh, wql, bq, 1.f,    // 5 <- ncu target
        nullptr, qh, ql, Hq, Dq, 0, 0, 0);
    mma_gemm<0><<<gP, 256, MM_SMEM>>>(hsh, hsl, wkh, wkl, bk, 1.f,
        nullptr, kh, kl, Hq, Dq, 0, 0, 0);
    mma_gemm<1><<<gP, 256, MM_SMEM>>>(hsh, hsl, w1h, w1l, nullptr, 1.f,
        hw1, nullptr, nullptr, Hq, Dq, 0, 0, 0);

    // scores = Q @ K^T / sqrt(D): per batch 2048x2048, K=512 (skip dead blocks)
    dim3 gS(Sq / 128, Sq / 128, Bq);
    mma_gemm<2><<<gS, 256, MM_SMEM>>>(qh, ql, kh, kl, nullptr,
        0.044194173824159216f, sc, nullptr, nullptr, Dq, Sq,
        (long long)Sq * Dq, (long long)Sq * Dq, (long long)Sq * Sq);

    transpose_hw1_kernel<<<dim3(Dq / 32, Sq / 32, Bq), dim3(32, 8)>>>();
    softmax_scores_kernel<<<MSq, 256>>>();

    // h = probs @ HSW1: per batch 2048x512, K=2048 clamped to len
    dim3 gH(Dq / 128, Sq / 128, Bq);
    mma_gemm<3><<<gH, 256, MM_SMEM>>>(ph, pl, h1th, h1tl, nullptr, 1.f,
        hbuf, nullptr, nullptr, Sq, Dq,
        (long long)Sq * Sq, (long long)Dq * Sq, (long long)Sq * Dq);

    ln_score_kernel<<<MSq, 128>>>(b1, lng, lnb, W2, b2, ts);
    rationale_kernel<<<Bq, 256>>>(ts, rat);
    token_probs_kernel<<<Bq, 256>>>(ts, tp);
    attended_pooled_kernel<<<dim3(Hq / 256, Bq), 256>>>(hs, att, pooled);
}

// round 7
// speedup vs baseline: 2.2897x; 1.4638x over previous
#include <cuda_runtime.h>
#include <cuda_fp16.h>
#include <math.h>
#include <stdint.h>

#define Bq 16
#define Sq 2048
#define Hq 1024
#define Dq 512
#define MSq (Bq * Sq)   // 32768

// ---------------- scratch (__device__ globals; no allocations) ----------------
__device__ __half g_hs_hi[(size_t)MSq * Hq];
__device__ __half g_hs_lo[(size_t)MSq * Hq];
__device__ __half g_wqT[(size_t)Dq * Hq];
__device__ __half g_wkT[(size_t)Dq * Hq];
__device__ __half g_w1T[(size_t)Dq * Hq];
__device__ __half g_q_hi[(size_t)MSq * Dq];
__device__ __half g_q_lo[(size_t)MSq * Dq];
__device__ __half g_k_hi[(size_t)MSq * Dq];          // B-side only: hi limb suffices
__device__ float  g_hw1[(size_t)MSq * Dq];           // fp32 [B*S, D]
__device__ __half g_hw1t[(size_t)Bq * Dq * Sq];      // [b][n][t], hi only (B-side)
__device__ float  g_scores[(size_t)Bq * Sq * Sq];
__device__ __half g_p_hi[(size_t)Bq * Sq * Sq];
__device__ __half g_p_lo[(size_t)Bq * Sq * Sq];
__device__ float  g_h[(size_t)MSq * Dq];
__device__ int    g_len[Bq];
__device__ float  g_ratlen[Bq];
__device__ int    g_spanstart[Bq];
__device__ int    g_spanlen[Bq];

// ---------------- helpers ----------------
__device__ __forceinline__ uint32_t smem_u32(const void* p) {
    uint32_t a;
    asm("{ .reg .u64 t; cvta.to.shared.u64 t, %1; cvt.u32.u64 %0, t; }" : "=r"(a) : "l"(p));
    return a;
}
__device__ __forceinline__ void cpa16(uint32_t s, const void* g) {
    asm volatile("cp.async.cg.shared.global [%0], [%1], 16;" :: "r"(s), "l"(g));
}
__device__ __forceinline__ void cpa_commit() {
    asm volatile("cp.async.commit_group;" ::: "memory");
}
template<int N> __device__ __forceinline__ void cpa_wait() {
    asm volatile("cp.async.wait_group %0;" :: "n"(N) : "memory");
}
__device__ __forceinline__ void ldm4(uint32_t* d, uint32_t a) {
    asm volatile("ldmatrix.sync.aligned.m8n8.x4.shared.b16 {%0,%1,%2,%3}, [%4];"
        : "=r"(d[0]), "=r"(d[1]), "=r"(d[2]), "=r"(d[3]) : "r"(a));
}
__device__ __forceinline__ void mma16816h(float* c, const uint32_t* a, const uint32_t* b) {
    asm volatile("mma.sync.aligned.m16n8k16.row.col.f32.f16.f16.f32 "
        "{%0,%1,%2,%3}, {%4,%5,%6,%7}, {%8,%9}, {%0,%1,%2,%3};"
        : "+f"(c[0]), "+f"(c[1]), "+f"(c[2]), "+f"(c[3])
        : "r"(a[0]), "r"(a[1]), "r"(a[2]), "r"(a[3]), "r"(b[0]), "r"(b[1]));
}
__device__ __forceinline__ void split2h(float v, __half& h, __half& l) {
    h = __float2half(v);
    l = __float2half(v - __half2float(h));
}
// SW128-style swizzle inside a 128-byte row: chunk' = chunk ^ (row & 7)
__device__ __forceinline__ uint32_t swz(int r, int chunk) {
    return ((uint32_t)r << 7) + (uint32_t)((chunk ^ (r & 7)) << 4);
}

// ---------------------------------------------------------------------------
// 2-pass split-fp16 mma.sync GEMM: C = alpha*((Ah+Al) @ Bh^T) (+ bias)
//   A: [M,K] K-major hi/lo fp16;  B: [N,K] K-major hi fp16.
// 128x128 tile, K-chunk 64, 2-stage cp.async (3 tiles x 16KB x 2 = 96KB).
// MODE 0: q proj  (half hi/lo out + bias; skip rows >= len[b])
// MODE 4: k proj  (half hi out + bias;    skip rows >= len[b])
// MODE 1: hw1 proj (f32 out;              skip rows >= len[b])
// MODE 2: scores  (f32 out, alpha;        skip m0>=len || n0>=len)
// MODE 3: probs   (f32 out;               skip m0>=len, clamp K to len)
// ---------------------------------------------------------------------------
#define MM_SMEM 98304

template<int MODE>
__global__ void __launch_bounds__(256)
mma_gemm(const __half* __restrict__ Ah, const __half* __restrict__ Al,
         const __half* __restrict__ Bh,
         const float* __restrict__ bias, float alpha,
         float* __restrict__ Cf, __half* __restrict__ Chi, __half* __restrict__ Clo,
         int K, int ldc, long long sA, long long sB, long long sC)
{
    extern __shared__ char dsm[];
    const uint32_t sb0 = smem_u32(dsm);
    const int tid  = threadIdx.x;
    const int lane = tid & 31;
    const int wid  = tid >> 5;
    const int wm   = wid & 1;
    const int wn   = wid >> 1;

    const long long z = blockIdx.z;
    const int m0 = blockIdx.y * 128;
    const int n0 = blockIdx.x * 128;

    int NK = K >> 6;
    if (MODE == 0 || MODE == 1 || MODE == 4) {
        if ((m0 & 2047) >= g_len[m0 >> 11]) return;
    } else if (MODE == 2) {
        const int len = g_len[z];
        if (m0 >= len || n0 >= len) return;
    } else {
        const int len = g_len[z];
        if (m0 >= len) return;
        const int nk2 = (len + 63) >> 6;
        if (nk2 < NK) NK = nk2;
    }

    const __half* pAh = Ah + z * sA;
    const __half* pAl = Al + z * sA;
    const __half* pBh = Bh + z * sB;

    const int r_ld  = tid >> 1;
    const int cu_ld = (tid & 1) << 2;
    const long long arow = (long long)(m0 + r_ld) * K;
    const long long brow = (long long)(n0 + r_ld) * K;

    auto issue = [&](int kt) {
        const uint32_t so = sb0 + (uint32_t)(kt & 1) * 49152u;
        const int k0 = kt << 6;
#pragma unroll
        for (int i = 0; i < 4; i++) {
            const int ch = cu_ld + i;
            const uint32_t sw = swz(r_ld, ch);
            const int go = k0 + ch * 8;
            cpa16(so +     0 + sw, pAh + arow + go);
            cpa16(so + 16384 + sw, pAl + arow + go);
            cpa16(so + 32768 + sw, pBh + brow + go);
        }
        cpa_commit();
    };

    float acc[4][4][4];
#pragma unroll
    for (int i = 0; i < 4; i++)
#pragma unroll
        for (int j = 0; j < 4; j++)
#pragma unroll
            for (int e = 0; e < 4; e++) acc[i][j][e] = 0.f;

    const int l15 = lane & 15, lhi = lane >> 4;
    int rA[4], rB[2];
#pragma unroll
    for (int mi = 0; mi < 4; mi++) rA[mi] = wm * 64 + mi * 16 + l15;
#pragma unroll
    for (int bj = 0; bj < 2; bj++) rB[bj] = wn * 32 + bj * 16 + l15;

    issue(0);

#pragma unroll 1
    for (int kt = 0; kt < NK; kt++) {
        if (kt + 1 < NK) { issue(kt + 1); cpa_wait<1>(); }
        else             { cpa_wait<0>(); }
        __syncthreads();

        const uint32_t uA = sb0 + (uint32_t)(kt & 1) * 49152u;
        const uint32_t uAl = uA + 16384, uBh = uA + 32768;

#pragma unroll
        for (int ks = 0; ks < 4; ks++) {
            const int ch = ks * 2 + lhi;
            uint32_t ah[4][4], al[4][4], bh[4][2];
#pragma unroll
            for (int mi = 0; mi < 4; mi++) ldm4(ah[mi], uA  + swz(rA[mi], ch));
#pragma unroll
            for (int mi = 0; mi < 4; mi++) ldm4(al[mi], uAl + swz(rA[mi], ch));
#pragma unroll
            for (int bj = 0; bj < 2; bj++) {
                uint32_t q[4];
                ldm4(q, uBh + swz(rB[bj], ch));
                bh[bj*2][0] = q[0]; bh[bj*2+1][0] = q[1];
                bh[bj*2][1] = q[2]; bh[bj*2+1][1] = q[3];
            }
#pragma unroll
            for (int mi = 0; mi < 4; mi++)
#pragma unroll
                for (int nj = 0; nj < 4; nj++) {
                    mma16816h(acc[mi][nj], ah[mi], bh[nj]);
                    mma16816h(acc[mi][nj], al[mi], bh[nj]);
                }
        }
        __syncthreads();
    }

    // ---- epilogue ----
    float*  pCf  = Cf  + z * sC;
    __half* pChi = Chi + z * sC;
    __half* pClo = Clo + z * sC;
    const int r4 = lane >> 2, c2 = (lane & 3) << 1;
#pragma unroll
    for (int mi = 0; mi < 4; mi++) {
        const long long gm = (long long)(m0 + wm * 64 + mi * 16 + r4);
#pragma unroll
        for (int nj = 0; nj < 4; nj++) {
            const int gn = n0 + wn * 32 + nj * 8 + c2;
            float v0 = alpha * acc[mi][nj][0];
            float v1 = alpha * acc[mi][nj][1];
            float v2 = alpha * acc[mi][nj][2];
            float v3 = alpha * acc[mi][nj][3];
            if (MODE == 0 || MODE == 4) {
                const float bx = bias[gn], by = bias[gn + 1];
                v0 += bx; v1 += by; v2 += bx; v3 += by;
            }
            const long long o0 = gm * ldc + gn;
            const long long o1 = (gm + 8) * ldc + gn;
            if (MODE == 0) {
                union { __half h[2]; uint32_t u; } ph, pl;
                __half h0,l0,h1,l1;
                split2h(v0,h0,l0); split2h(v1,h1,l1);
                ph.h[0]=h0; ph.h[1]=h1; pl.h[0]=l0; pl.h[1]=l1;
                *(uint32_t*)&pChi[o0] = ph.u; *(uint32_t*)&pClo[o0] = pl.u;
                split2h(v2,h0,l0); split2h(v3,h1,l1);
                ph.h[0]=h0; ph.h[1]=h1; pl.h[0]=l0; pl.h[1]=l1;
                *(uint32_t*)&pChi[o1] = ph.u; *(uint32_t*)&pClo[o1] = pl.u;
            } else if (MODE == 4) {
                union { __half h[2]; uint32_t u; } ph;
                ph.h[0] = __float2half(v0); ph.h[1] = __float2half(v1);
                *(uint32_t*)&pChi[o0] = ph.u;
                ph.h[0] = __float2half(v2); ph.h[1] = __float2half(v3);
                *(uint32_t*)&pChi[o1] = ph.u;
            } else {
                *(float2*)&pCf[o0] = make_float2(v0, v1);
                *(float2*)&pCf[o1] = make_float2(v2, v3);
            }
        }
    }
}

// ---------------- conversions ----------------
__global__ void convert_hs_kernel(const float* __restrict__ hs) {
    const size_t i = ((size_t)blockIdx.x * 256 + threadIdx.x) * 8;
    const int row = (int)(i >> 10);
    if ((row & 2047) >= g_len[row >> 11]) return;
    float4 a = *(const float4*)(hs + i);
    float4 b = *(const float4*)(hs + i + 4);
    union { uint4 q; __half v[8]; } hi, lo;
    split2h(a.x, hi.v[0], lo.v[0]); split2h(a.y, hi.v[1], lo.v[1]);
    split2h(a.z, hi.v[2], lo.v[2]); split2h(a.w, hi.v[3], lo.v[3]);
    split2h(b.x, hi.v[4], lo.v[4]); split2h(b.y, hi.v[5], lo.v[5]);
    split2h(b.z, hi.v[6], lo.v[6]); split2h(b.w, hi.v[7], lo.v[7]);
    *(uint4*)&g_hs_hi[i] = hi.q;
    *(uint4*)&g_hs_lo[i] = lo.q;
}

// W [Hq, Dq] fp32 -> Wt [Dq, Hq] fp16 (hi only — B-side operand)
__global__ void convert_wT_kernel(const float* __restrict__ W, __half* __restrict__ T) {
    __shared__ float t[32][33];
    const int nx = blockIdx.x * 32, ky = blockIdx.y * 32;
    const int x = threadIdx.x, y = threadIdx.y;
#pragma unroll
    for (int i = 0; i < 32; i += 8)
        t[y + i][x] = W[(size_t)(ky + y + i) * Dq + nx + x];
    __syncthreads();
#pragma unroll
    for (int i = 0; i < 32; i += 8)
        T[(size_t)(nx + y + i) * Hq + ky + x] = __float2half(t[x][y + i]);
}

// g_hw1 [(b*S+t), n] fp32 -> g_hw1t [b][n][t] fp16 hi (B-side operand)
__global__ void transpose_hw1_kernel() {
    __shared__ float t[32][33];
    const int b = blockIdx.z;
    const int nx = blockIdx.x * 32, sy = blockIdx.y * 32;
    const int nk64 = (g_len[b] + 63) & ~63;
    if (sy >= nk64) return;
    const int x = threadIdx.x, y = threadIdx.y;
#pragma unroll
    for (int i = 0; i < 32; i += 8)
        t[y + i][x] = g_hw1[(size_t)(b * Sq + sy + y + i) * Dq + nx + x];
    __syncthreads();
#pragma unroll
    for (int i = 0; i < 32; i += 8)
        g_hw1t[(size_t)(b * Dq + nx + y + i) * Sq + sy + x] = __float2half(t[x][y + i]);
}

// ---------------- non-GEMM kernels ----------------
__global__ void lens_kernel(const int* __restrict__ mask) {
    __shared__ int red[256];
    const int b = blockIdx.x, tid = threadIdx.x;
    int s = 0;
    for (int t = tid; t < Sq; t += 256) s += mask[b * Sq + t];
    red[tid] = s; __syncthreads();
    for (int w = 128; w > 0; w >>= 1) { if (tid < w) red[tid] += red[tid + w]; __syncthreads(); }
    if (tid == 0) g_len[b] = red[0];
}

__global__ void softmax_scores_kernel() {
    __shared__ float buf[Sq];
    __shared__ float red[256];
    const int row = blockIdx.x;
    const int len = g_len[row >> 11];
    if ((row & 2047) >= len) return;
    const int nk64 = (len + 63) & ~63;
    const float* x = g_scores + (size_t)row * Sq;
    const int tid = threadIdx.x;

    float m = -1e30f;
    for (int t = tid; t < len; t += 256) { float v = x[t]; buf[t] = v; m = fmaxf(m, v); }
    red[tid] = m; __syncthreads();
    for (int w = 128; w > 0; w >>= 1) { if (tid < w) red[tid] = fmaxf(red[tid], red[tid + w]); __syncthreads(); }
    m = red[0]; __syncthreads();

    float s = 0.f;
    for (int t = tid; t < len; t += 256) { float e = expf(buf[t] - m); buf[t] = e; s += e; }
    red[tid] = s; __syncthreads();
    for (int w = 128; w > 0; w >>= 1) { if (tid < w) red[tid] += red[tid + w]; __syncthreads(); }
    const float Z = red[0];

    for (int t = tid; t < nk64; t += 256) {
        const float p = (t < len) ? buf[t] / Z : 0.f;
        __half h, l; split2h(p, h, l);
        g_p_hi[(size_t)row * Sq + t] = h;
        g_p_lo[(size_t)row * Sq + t] = l;
    }
}

__global__ void ln_score_kernel(const float* __restrict__ b1,
                                const float* __restrict__ lng, const float* __restrict__ lnb,
                                const float* __restrict__ W2,  const float* __restrict__ b2,
                                float* __restrict__ ts_out)
{
    __shared__ float red[128];
    const int row = blockIdx.x;
    const int tid = threadIdx.x;
    const int b = row >> 11, sIdx = row & (Sq - 1);
    if (sIdx >= g_len[b]) { if (tid == 0) ts_out[row] = -10000.f; return; }
    const float* h = g_h + (size_t)row * Dq;

    float v[4];
    float s = 0.f;
#pragma unroll
    for (int i = 0; i < 4; i++) { v[i] = h[tid + i * 128] + b1[tid + i * 128]; s += v[i]; }
    red[tid] = s; __syncthreads();
    for (int w = 64; w > 0; w >>= 1) { if (tid < w) red[tid] += red[tid + w]; __syncthreads(); }
    const float mu = red[0] / (float)Dq;
    __syncthreads();

    s = 0.f;
#pragma unroll
    for (int i = 0; i < 4; i++) { float d = v[i] - mu; s += d * d; }
    red[tid] = s; __syncthreads();
    for (int w = 64; w > 0; w >>= 1) { if (tid < w) red[tid] += red[tid + w]; __syncthreads(); }
    const float rstd = rsqrtf(red[0] / (float)Dq + 1e-5f);
    __syncthreads();

    s = 0.f;
#pragma unroll
    for (int i = 0; i < 4; i++) {
        const int d = tid + i * 128;
        float y = (v[i] - mu) * rstd * lng[d] + lnb[d];
        y = fmaxf(y, 0.f);
        s += y * W2[d];
    }
    red[tid] = s; __syncthreads();
    for (int w = 64; w > 0; w >>= 1) { if (tid < w) red[tid] += red[tid + w]; __syncthreads(); }
    if (tid == 0) ts_out[row] = red[0] + b2[0];
}

__global__ void rationale_kernel(const float* __restrict__ ts_all, float* __restrict__ rat_out)
{
    __shared__ float cum[Sq];
    __shared__ float rv[256];
    __shared__ int   ri[256];
    const int b = blockIdx.x, tid = threadIdx.x;
    const float* ts = ts_all + b * Sq;

    for (int t = tid; t < Sq; t += 256) cum[t] = ts[t];
    __syncthreads();
    if (tid == 0) { float a = 0.f; for (int t = 0; t < Sq; t++) { a += cum[t]; cum[t] = a; } }
    __syncthreads();

    const int vl = g_len[b];
    float best = -1e38f; int bi = 1 << 30;
    for (int idx = tid; idx < 18 * Sq; idx += 256) {
        const int Li = idx >> 11;
        const int s  = idx & (Sq - 1);
        const int L  = 3 + Li;
        if (L <= vl && s <= vl - L) {
            int e = s + L - 1; if (e > Sq - 1) e = Sq - 1;
            const float val = cum[e] / (float)L + 0.01f * ((float)L / 20.0f);
            if (val > best || (val == best && idx < bi)) { best = val; bi = idx; }
        }
    }
    rv[tid] = best; ri[tid] = bi; __syncthreads();
    for (int w = 128; w > 0; w >>= 1) {
        if (tid < w) {
            if (rv[tid + w] > rv[tid] || (rv[tid + w] == rv[tid] && ri[tid + w] < ri[tid])) {
                rv[tid] = rv[tid + w]; ri[tid] = ri[tid + w];
            }
        }
        __syncthreads();
    }
    int idx = ri[0];
    if (idx >= 18 * Sq) idx = 0;
    const int bestL = 3 + (idx >> 11);
    const int bests = idx & (Sq - 1);
    const bool shortc = (vl <= 3);

    for (int t = tid; t < Sq; t += 256) {
        const float r = shortc ? ((t < vl) ? 1.f : 0.f)
                               : ((t >= bests && t < bests + bestL) ? 1.f : 0.f);
        rat_out[b * Sq + t] = r;
    }
    if (tid == 0) {
        g_ratlen[b]    = shortc ? (float)vl : (float)bestL;
        g_spanstart[b] = shortc ? 0 : bests;
        g_spanlen[b]   = shortc ? vl : bestL;
    }
}

__global__ void token_probs_kernel(const float* __restrict__ ts, float* __restrict__ tp)
{
    __shared__ float buf[Sq];
    __shared__ float red[256];
    const int b = blockIdx.x, tid = threadIdx.x;
    const float* x = ts + b * Sq;

    float m = -1e30f;
    for (int t = tid; t < Sq; t += 256) { float v = x[t]; buf[t] = v; m = fmaxf(m, v); }
    red[tid] = m; __syncthreads();
    for (int w = 128; w > 0; w >>= 1) { if (tid < w) red[tid] = fmaxf(red[tid], red[tid + w]); __syncthreads(); }
    m = red[0]; __syncthreads();

    float s = 0.f;
    for (int t = tid; t < Sq; t += 256) { float e = expf(buf[t] - m); buf[t] = e; s += e; }
    red[tid] = s; __syncthreads();
    for (int w = 128; w > 0; w >>= 1) { if (tid < w) red[tid] += red[tid + w]; __syncthreads(); }
    const float Z = red[0];

    for (int t = tid; t < Sq; t += 256) tp[b * Sq + t] = buf[t] / Z;
}

__global__ void attended_pooled_kernel(const float* __restrict__ hs,
                                       float* __restrict__ att, float* __restrict__ pooled)
{
    const int b = blockIdx.y;
    const int h = blockIdx.x * 256 + threadIdx.x;
    const int ss = g_spanstart[b];
    const int se = ss + g_spanlen[b];

    const float* hsb = hs  + (size_t)b * Sq * Hq + h;
    float*      attb = att + (size_t)b * Sq * Hq + h;
    float acc = 0.f;
    for (int s = 0; s < ss; s++)  attb[(size_t)s * Hq] = 0.f;
    for (int s = ss; s < se; s++) { float v = hsb[(size_t)s * Hq]; attb[(size_t)s * Hq] = v; acc += v; }
    for (int s = se; s < Sq; s++) attb[(size_t)s * Hq] = 0.f;
    pooled[b * Hq + h] = acc / (g_ratlen[b] + 1e-6f);
}

// ---------------------------------------------------------------------------
extern "C" void kernel_launch(void* const* d_in, const int* in_sizes, int n_in,
                              void* d_out, int out_size)
{
    (void)in_sizes; (void)n_in; (void)out_size;
    const float* hs  = (const float*)d_in[0];
    const int*   am  = (const int*)  d_in[1];
    const float* Wq  = (const float*)d_in[2];
    const float* bq  = (const float*)d_in[3];
    const float* Wk  = (const float*)d_in[4];
    const float* bk  = (const float*)d_in[5];
    const float* W1  = (const float*)d_in[6];
    const float* b1  = (const float*)d_in[7];
    const float* lng = (const float*)d_in[8];
    const float* lnb = (const float*)d_in[9];
    const float* W2  = (const float*)d_in[10];
    const float* b2  = (const float*)d_in[11];

    float* out    = (float*)d_out;
    float* ts     = out;
    float* rat    = out + (size_t)MSq;
    float* tp     = out + (size_t)2 * MSq;
    float* att    = out + (size_t)3 * MSq;
    float* pooled = out + (size_t)3 * MSq + (size_t)MSq * Hq;

    __half *hsh, *hsl, *wq, *wk, *w1, *qh, *ql, *kh, *h1t, *ph, *pl;
    float *hw1, *sc, *hbuf;
    cudaGetSymbolAddress((void**)&hsh, g_hs_hi); cudaGetSymbolAddress((void**)&hsl, g_hs_lo);
    cudaGetSymbolAddress((void**)&wq,  g_wqT);   cudaGetSymbolAddress((void**)&wk,  g_wkT);
    cudaGetSymbolAddress((void**)&w1,  g_w1T);
    cudaGetSymbolAddress((void**)&qh,  g_q_hi);  cudaGetSymbolAddress((void**)&ql,  g_q_lo);
    cudaGetSymbolAddress((void**)&kh,  g_k_hi);
    cudaGetSymbolAddress((void**)&h1t, g_hw1t);
    cudaGetSymbolAddress((void**)&ph,  g_p_hi);  cudaGetSymbolAddress((void**)&pl,  g_p_lo);
    cudaGetSymbolAddress((void**)&hw1, g_hw1);
    cudaGetSymbolAddress((void**)&sc,  g_scores);
    cudaGetSymbolAddress((void**)&hbuf, g_h);

    cudaFuncSetAttribute(mma_gemm<0>, cudaFuncAttributeMaxDynamicSharedMemorySize, MM_SMEM);
    cudaFuncSetAttribute(mma_gemm<1>, cudaFuncAttributeMaxDynamicSharedMemorySize, MM_SMEM);
    cudaFuncSetAttribute(mma_gemm<2>, cudaFuncAttributeMaxDynamicSharedMemorySize, MM_SMEM);
    cudaFuncSetAttribute(mma_gemm<3>, cudaFuncAttributeMaxDynamicSharedMemorySize, MM_SMEM);
    cudaFuncSetAttribute(mma_gemm<4>, cudaFuncAttributeMaxDynamicSharedMemorySize, MM_SMEM);

    lens_kernel<<<Bq, 256>>>(am);
    dim3 wg(Dq / 32, Hq / 32);
    convert_wT_kernel<<<wg, dim3(32, 8)>>>(Wq, wq);
    convert_wT_kernel<<<wg, dim3(32, 8)>>>(Wk, wk);
    convert_wT_kernel<<<wg, dim3(32, 8)>>>(W1, w1);
    convert_hs_kernel<<<(int)(((size_t)MSq * Hq) / 8 / 256), 256>>>(hs);

    // projections: M=32768, N=512, K=1024 (row-blocks >= len[b] skipped)
    dim3 gP(Dq / 128, MSq / 128, 1);
    mma_gemm<0><<<gP, 256, MM_SMEM>>>(hsh, hsl, wq, bq, 1.f,
        nullptr, qh, ql, Hq, Dq, 0, 0, 0);
    mma_gemm<4><<<gP, 256, MM_SMEM>>>(hsh, hsl, wk, bk, 1.f,
        nullptr, kh, nullptr, Hq, Dq, 0, 0, 0);
    mma_gemm<1><<<gP, 256, MM_SMEM>>>(hsh, hsl, w1, nullptr, 1.f,
        hw1, nullptr, nullptr, Hq, Dq, 0, 0, 0);

    // scores = Q @ K^T / sqrt(D): per batch 2048x2048, K=512 (skip dead blocks)
    dim3 gS(Sq / 128, Sq / 128, Bq);
    mma_gemm<2><<<gS, 256, MM_SMEM>>>(qh, ql, kh, nullptr,
        0.044194173824159216f, sc, nullptr, nullptr, Dq, Sq,
        (long long)Sq * Dq, (long long)Sq * Dq, (long long)Sq * Sq);

    transpose_hw1_kernel<<<dim3(Dq / 32, Sq / 32, Bq), dim3(32, 8)>>>();
    softmax_scores_kernel<<<MSq, 256>>>();

    // h = probs @ HSW1: per batch 2048x512, K=2048 clamped to len
    dim3 gH(Dq / 128, Sq / 128, Bq);
    mma_gemm<3><<<gH, 256, MM_SMEM>>>(ph, pl, h1t, nullptr, 1.f,
        hbuf, nullptr, nullptr, Sq, Dq,
        (long long)Sq * Sq, (long long)Dq * Sq, (long long)Sq * Dq);

    ln_score_kernel<<<MSq, 128>>>(b1, lng, lnb, W2, b2, ts);
    rationale_kernel<<<Bq, 256>>>(ts, rat);
    token_probs_kernel<<<Bq, 256>>>(ts, tp);
    attended_pooled_kernel<<<dim3(Hq / 256, Bq), 256>>>(hs, att, pooled);
}